// round 1
// baseline (speedup 1.0000x reference)
#include <cuda_runtime.h>
#include <cuda_bf16.h>
#include <math.h>

// ---------------------------------------------------------------------------
// GCN: 3x GCNConv (128->64->64->64) + concat(192) @ Wl(192x8) + log_softmax
// out[d] = dis[d] * ( sum_{edges s->d} h'[s] + h'[d] ) + b,  h' = dis * (x @ W)
// ---------------------------------------------------------------------------

#define N_NODES_MAX 50000
#define FDIM 64

__device__ float g_dis[N_NODES_MAX];
__device__ float g_h  [N_NODES_MAX * FDIM];
__device__ float g_agg[N_NODES_MAX * FDIM];
__device__ float g_x1 [N_NODES_MAX * FDIM];
__device__ float g_x2 [N_NODES_MAX * FDIM];
__device__ float g_x3 [N_NODES_MAX * FDIM];

// ---- degree ----------------------------------------------------------------
__global__ void k_init_deg(float* __restrict__ deg, int n) {
    int i = blockIdx.x * blockDim.x + threadIdx.x;
    if (i < n) deg[i] = 1.0f;   // self-loop
}

__global__ void k_count_deg(const int* __restrict__ dst, float* __restrict__ deg, int e) {
    int i = blockIdx.x * blockDim.x + threadIdx.x;
    if (i < e) atomicAdd(&deg[dst[i]], 1.0f);
}

__global__ void k_rsqrt(float* __restrict__ deg, int n) {
    int i = blockIdx.x * blockDim.x + threadIdx.x;
    if (i < n) deg[i] = rsqrtf(deg[i]);
}

// ---- GEMM  h' = dis * (X @ W), written to both h and agg -------------------
// X: [M, K] row-major, W: [K, 64] row-major.
template <int K, int ROWS>
__global__ void __launch_bounds__(256)
k_gemm_scale(const float* __restrict__ X, const float* __restrict__ W,
             const float* __restrict__ dis,
             float* __restrict__ h, float* __restrict__ agg, int M) {
    constexpr int TPR = 256 / ROWS;   // threads per row
    constexpr int CPT = 64 / TPR;     // columns per thread
    constexpr int NV  = CPT / 4;      // float4s per thread

    __shared__ float Xs[ROWS][K + 1];
    __shared__ float Ws[K * 64];

    int tid = threadIdx.x;
    int m0  = blockIdx.x * ROWS;

    // load W tile (K*64 floats) as float4
    const float4* W4  = (const float4*)W;
    float4*       Ws4 = (float4*)Ws;
    #pragma unroll 1
    for (int i = tid; i < K * 16; i += 256) Ws4[i] = W4[i];

    // load X tile (ROWS x K) with row padding (scalar stores into padded smem)
    constexpr int KV = K / 4;
    #pragma unroll 1
    for (int i = tid; i < ROWS * KV; i += 256) {
        int r = i / KV, c = i % KV;
        int gr = m0 + r;
        float4 v = make_float4(0.f, 0.f, 0.f, 0.f);
        if (gr < M) v = __ldg((const float4*)(X + (size_t)gr * K) + c);
        Xs[r][c * 4 + 0] = v.x;
        Xs[r][c * 4 + 1] = v.y;
        Xs[r][c * 4 + 2] = v.z;
        Xs[r][c * 4 + 3] = v.w;
    }
    __syncthreads();

    int r  = tid / TPR;
    int cg = tid % TPR;

    float4 acc[NV];
    #pragma unroll
    for (int v = 0; v < NV; v++) acc[v] = make_float4(0.f, 0.f, 0.f, 0.f);

    #pragma unroll 16
    for (int k = 0; k < K; k++) {
        float a = Xs[r][k];
        #pragma unroll
        for (int v = 0; v < NV; v++) {
            float4 w = Ws4[k * 16 + cg * NV + v];
            acc[v].x += a * w.x;
            acc[v].y += a * w.y;
            acc[v].z += a * w.z;
            acc[v].w += a * w.w;
        }
    }

    int gr = m0 + r;
    if (gr < M) {
        float dd = __ldg(dis + gr);
        float4* hp = (float4*)(h   + (size_t)gr * 64) + cg * NV;
        float4* ap = (float4*)(agg + (size_t)gr * 64) + cg * NV;
        #pragma unroll
        for (int v = 0; v < NV; v++) {
            acc[v].x *= dd; acc[v].y *= dd; acc[v].z *= dd; acc[v].w *= dd;
            hp[v] = acc[v];
            ap[v] = acc[v];
        }
    }
}

// ---- edge scatter: agg[dst] += h'[src]  (vector RED) -----------------------
__global__ void __launch_bounds__(256)
k_scatter(const int* __restrict__ src, const int* __restrict__ dst,
          const float* __restrict__ h, float* __restrict__ agg, int E) {
    int e = blockIdx.x * 16 + (threadIdx.x >> 4);
    if (e >= E) return;
    int lane = threadIdx.x & 15;
    int s = __ldg(src + e);
    int d = __ldg(dst + e);
    float4 v = __ldg((const float4*)(h + (size_t)s * 64) + lane);
    float* p = agg + (size_t)d * 64 + lane * 4;
    asm volatile("red.global.add.v4.f32 [%0], {%1,%2,%3,%4};"
                 :: "l"(p), "f"(v.x), "f"(v.y), "f"(v.z), "f"(v.w)
                 : "memory");
}

// ---- finalize: xout = [relu](dis * agg + b) --------------------------------
__global__ void __launch_bounds__(256)
k_finalize(const float* __restrict__ agg, const float* __restrict__ dis,
           const float* __restrict__ b, float* __restrict__ xout,
           int M, int do_relu) {
    int i = blockIdx.x * blockDim.x + threadIdx.x;
    if (i >= M * 16) return;
    int row = i >> 4;
    int c4  = i & 15;
    float4 v  = __ldg((const float4*)agg + i);
    float  dd = __ldg(dis + row);
    float4 bb = __ldg((const float4*)b + c4);
    v.x = v.x * dd + bb.x;
    v.y = v.y * dd + bb.y;
    v.z = v.z * dd + bb.z;
    v.w = v.w * dd + bb.w;
    if (do_relu) {
        v.x = fmaxf(v.x, 0.f); v.y = fmaxf(v.y, 0.f);
        v.z = fmaxf(v.z, 0.f); v.w = fmaxf(v.w, 0.f);
    }
    ((float4*)xout)[i] = v;
}

// ---- classifier: log_softmax(concat(x1,x2,x3) @ Wl + bl) -------------------
// one warp per node; Wl transposed into smem for conflict-free reads
__global__ void __launch_bounds__(256)
k_classify(const float* __restrict__ x1, const float* __restrict__ x2,
           const float* __restrict__ x3, const float* __restrict__ Wl,
           const float* __restrict__ bl, float* __restrict__ out, int M) {
    __shared__ float sW[8 * 192];   // sW[c*192 + f]
    __shared__ float sb[8];
    int tid = threadIdx.x;
    for (int i = tid; i < 192 * 8; i += 256) {
        int f = i >> 3, c = i & 7;
        sW[c * 192 + f] = Wl[i];
    }
    if (tid < 8) sb[tid] = bl[tid];
    __syncthreads();

    int node = blockIdx.x * 8 + (tid >> 5);
    int lane = tid & 31;
    if (node >= M) return;

    float f0 = __ldg(x1 + (size_t)node * 64 + lane);
    float f1 = __ldg(x1 + (size_t)node * 64 + lane + 32);
    float f2 = __ldg(x2 + (size_t)node * 64 + lane);
    float f3 = __ldg(x2 + (size_t)node * 64 + lane + 32);
    float f4 = __ldg(x3 + (size_t)node * 64 + lane);
    float f5 = __ldg(x3 + (size_t)node * 64 + lane + 32);

    float acc[8];
    #pragma unroll
    for (int c = 0; c < 8; c++) {
        const float* w = sW + c * 192;
        acc[c] = f0 * w[lane]       + f1 * w[lane + 32]
               + f2 * w[lane + 64]  + f3 * w[lane + 96]
               + f4 * w[lane + 128] + f5 * w[lane + 160];
    }
    #pragma unroll
    for (int off = 16; off; off >>= 1) {
        #pragma unroll
        for (int c = 0; c < 8; c++)
            acc[c] += __shfl_down_sync(0xffffffffu, acc[c], off);
    }
    if (lane == 0) {
        float m = -INFINITY;
        #pragma unroll
        for (int c = 0; c < 8; c++) { acc[c] += sb[c]; m = fmaxf(m, acc[c]); }
        float s = 0.f;
        #pragma unroll
        for (int c = 0; c < 8; c++) s += expf(acc[c] - m);
        float lse = logf(s) + m;
        #pragma unroll
        for (int c = 0; c < 8; c++) out[(size_t)node * 8 + c] = acc[c] - lse;
    }
}

// ---------------------------------------------------------------------------
extern "C" void kernel_launch(void* const* d_in, const int* in_sizes, int n_in,
                              void* d_out, int out_size) {
    const float* x  = (const float*)d_in[0];
    const int*   ei = (const int*)  d_in[1];
    const float* W1 = (const float*)d_in[2];
    const float* b1 = (const float*)d_in[3];
    const float* W2 = (const float*)d_in[4];
    const float* b2 = (const float*)d_in[5];
    const float* W3 = (const float*)d_in[6];
    const float* b3 = (const float*)d_in[7];
    const float* Wl = (const float*)d_in[8];
    const float* bl = (const float*)d_in[9];
    float* out = (float*)d_out;

    int N = in_sizes[0] / 128;
    int E = in_sizes[1] / 2;
    const int* src = ei;
    const int* dst = ei + E;

    float *dis, *h, *agg, *x1, *x2, *x3;
    cudaGetSymbolAddress((void**)&dis, g_dis);
    cudaGetSymbolAddress((void**)&h,   g_h);
    cudaGetSymbolAddress((void**)&agg, g_agg);
    cudaGetSymbolAddress((void**)&x1,  g_x1);
    cudaGetSymbolAddress((void**)&x2,  g_x2);
    cudaGetSymbolAddress((void**)&x3,  g_x3);

    int nb  = (N + 255) / 256;
    int eb  = (E + 255) / 256;
    int esb = (E + 15) / 16;
    int fb  = (N * 16 + 255) / 256;

    // normalization
    k_init_deg<<<nb, 256>>>(dis, N);
    k_count_deg<<<eb, 256>>>(dst, dis, E);
    k_rsqrt<<<nb, 256>>>(dis, N);

    // layer 1: 128 -> 64, relu
    k_gemm_scale<128, 16><<<(N + 15) / 16, 256>>>(x, W1, dis, h, agg, N);
    k_scatter<<<esb, 256>>>(src, dst, h, agg, E);
    k_finalize<<<fb, 256>>>(agg, dis, b1, x1, N, 1);

    // layer 2: 64 -> 64, relu
    k_gemm_scale<64, 32><<<(N + 31) / 32, 256>>>(x1, W2, dis, h, agg, N);
    k_scatter<<<esb, 256>>>(src, dst, h, agg, E);
    k_finalize<<<fb, 256>>>(agg, dis, b2, x2, N, 1);

    // layer 3: 64 -> 64, no relu
    k_gemm_scale<64, 32><<<(N + 31) / 32, 256>>>(x2, W3, dis, h, agg, N);
    k_scatter<<<esb, 256>>>(src, dst, h, agg, E);
    k_finalize<<<fb, 256>>>(agg, dis, b3, x3, N, 0);

    // classifier
    k_classify<<<(N + 7) / 8, 256>>>(x1, x2, x3, Wl, bl, out, N);
}

// round 2
// speedup vs baseline: 1.5775x; 1.5775x over previous
#include <cuda_runtime.h>
#include <cuda_bf16.h>
#include <math.h>

// ---------------------------------------------------------------------------
// GCN: 3x GCNConv (128->64->64->64) + concat(192) @ Wl(192x8) + log_softmax
// out[d] = dis[d] * ( sum_{edges s->d} h'[s] + h'[d] ) + b,  h' = dis * (x @ W)
// Layer k>1 input finalize (relu(dis*agg+b)) fused into GEMM A-tile load.
// ---------------------------------------------------------------------------

#define N_NODES_MAX 50000
#define FDIM 64

__device__ float g_dis [N_NODES_MAX];
__device__ float g_h   [N_NODES_MAX * FDIM];
__device__ float g_aggA[N_NODES_MAX * FDIM];
__device__ float g_aggB[N_NODES_MAX * FDIM];
__device__ float g_x1  [N_NODES_MAX * FDIM];
__device__ float g_x2  [N_NODES_MAX * FDIM];

// ---- degree ----------------------------------------------------------------
__global__ void k_init_deg(float* __restrict__ deg, int n) {
    int i = blockIdx.x * blockDim.x + threadIdx.x;
    if (i < n) deg[i] = 1.0f;   // self-loop
}

__global__ void k_count_deg(const int* __restrict__ dst, float* __restrict__ deg, int e) {
    int i = blockIdx.x * blockDim.x + threadIdx.x;
    if (i < e) atomicAdd(&deg[dst[i]], 1.0f);
}

__global__ void k_rsqrt(float* __restrict__ deg, int n) {
    int i = blockIdx.x * blockDim.x + threadIdx.x;
    if (i < n) deg[i] = rsqrtf(deg[i]);
}

// ---- GEMM  h' = dis * (A @ W) -> h, agg_out --------------------------------
// A is either raw X (FUSE=0) or agg_in, finalized on the fly:
//   a = relu(dis*agg_in + b_in), also saved to x_save (activation for classifier).
// Tile: 64 rows x 64 cols per block, 256 threads, 4x4 register blocking,
// K processed in chunks of 64.
template <int K, bool FUSE>
__global__ void __launch_bounds__(256)
k_gemm(const float* __restrict__ Xin, const float* __restrict__ W,
       const float* __restrict__ dis, const float* __restrict__ b_in,
       float* __restrict__ x_save,
       float* __restrict__ h, float* __restrict__ agg_out, int M) {
    constexpr int NCH = K / 64;           // K chunks of 64
    __shared__ float4 Xs4[64 * 16];       // 64 rows x 64 cols (chunk)
    __shared__ float4 Ws4[64 * 16];       // 64 k x 64 cols (chunk)

    int tid = threadIdx.x;
    int m0  = blockIdx.x * 64;
    int r4  = tid >> 4;    // row group 0..15 (4 rows each)
    int c4  = tid & 15;    // col group 0..15 (4 cols each)

    float4 acc[4];
    #pragma unroll
    for (int j = 0; j < 4; j++) acc[j] = make_float4(0.f, 0.f, 0.f, 0.f);

    const float4* W4 = (const float4*)W;

    #pragma unroll
    for (int ch = 0; ch < NCH; ch++) {
        // --- load A chunk (64 rows x 64 cols), optionally finalizing ---
        #pragma unroll
        for (int it = 0; it < 4; it++) {
            int i = tid + it * 256;           // 0..1023
            int r = i >> 4, c = i & 15;
            int gr = m0 + r;
            float4 v = make_float4(0.f, 0.f, 0.f, 0.f);
            if (gr < M) {
                v = __ldg((const float4*)(Xin + (size_t)gr * K) + ch * 16 + c);
                if (FUSE) {
                    float  dd = __ldg(dis + gr);
                    float4 bb = __ldg((const float4*)b_in + c);
                    v.x = fmaxf(v.x * dd + bb.x, 0.f);
                    v.y = fmaxf(v.y * dd + bb.y, 0.f);
                    v.z = fmaxf(v.z * dd + bb.z, 0.f);
                    v.w = fmaxf(v.w * dd + bb.w, 0.f);
                    ((float4*)(x_save + (size_t)gr * 64))[c] = v;
                }
            }
            Xs4[r * 16 + c] = v;
        }
        // --- load W chunk (64 k x 64 cols) ---
        #pragma unroll
        for (int it = 0; it < 4; it++) {
            int i = tid + it * 256;
            Ws4[i] = __ldg(W4 + ch * 1024 + i);
        }
        __syncthreads();

        // --- 4x4 register-blocked accumulate over 64 k ---
        #pragma unroll
        for (int k4 = 0; k4 < 16; k4++) {
            float4 a0 = Xs4[(r4 * 4 + 0) * 16 + k4];
            float4 a1 = Xs4[(r4 * 4 + 1) * 16 + k4];
            float4 a2 = Xs4[(r4 * 4 + 2) * 16 + k4];
            float4 a3 = Xs4[(r4 * 4 + 3) * 16 + k4];
            float4 w0 = Ws4[(k4 * 4 + 0) * 16 + c4];
            float4 w1 = Ws4[(k4 * 4 + 1) * 16 + c4];
            float4 w2 = Ws4[(k4 * 4 + 2) * 16 + c4];
            float4 w3 = Ws4[(k4 * 4 + 3) * 16 + c4];
            #define ROWFMA(J, A)                                               \
                acc[J].x += A.x * w0.x + A.y * w1.x + A.z * w2.x + A.w * w3.x; \
                acc[J].y += A.x * w0.y + A.y * w1.y + A.z * w2.y + A.w * w3.y; \
                acc[J].z += A.x * w0.z + A.y * w1.z + A.z * w2.z + A.w * w3.z; \
                acc[J].w += A.x * w0.w + A.y * w1.w + A.z * w2.w + A.w * w3.w;
            ROWFMA(0, a0) ROWFMA(1, a1) ROWFMA(2, a2) ROWFMA(3, a3)
            #undef ROWFMA
        }
        if (ch + 1 < NCH) __syncthreads();
    }

    // --- epilogue: scale by dis, write h and agg_out (self-loop init) ---
    #pragma unroll
    for (int j = 0; j < 4; j++) {
        int gr = m0 + r4 * 4 + j;
        if (gr < M) {
            float dd = __ldg(dis + gr);
            float4 v = acc[j];
            v.x *= dd; v.y *= dd; v.z *= dd; v.w *= dd;
            ((float4*)(h       + (size_t)gr * 64))[c4] = v;
            ((float4*)(agg_out + (size_t)gr * 64))[c4] = v;
        }
    }
}

// ---- edge scatter: agg[dst] += h'[src]  (vector RED) -----------------------
__global__ void __launch_bounds__(256)
k_scatter(const int* __restrict__ src, const int* __restrict__ dst,
          const float* __restrict__ h, float* __restrict__ agg, int E) {
    int e = blockIdx.x * 16 + (threadIdx.x >> 4);
    if (e >= E) return;
    int lane = threadIdx.x & 15;
    int s = __ldg(src + e);
    int d = __ldg(dst + e);
    float4 v = __ldg((const float4*)(h + (size_t)s * 64) + lane);
    float* p = agg + (size_t)d * 64 + lane * 4;
    asm volatile("red.global.add.v4.f32 [%0], {%1,%2,%3,%4};"
                 :: "l"(p), "f"(v.x), "f"(v.y), "f"(v.z), "f"(v.w)
                 : "memory");
}

// ---- classifier: log_softmax(concat(x1,x2,x3) @ Wl + bl) -------------------
// x3 = dis*agg + b3 applied inline (no relu). One warp per node.
__global__ void __launch_bounds__(256)
k_classify(const float* __restrict__ x1, const float* __restrict__ x2,
           const float* __restrict__ agg, const float* __restrict__ dis,
           const float* __restrict__ b3, const float* __restrict__ Wl,
           const float* __restrict__ bl, float* __restrict__ out, int M) {
    __shared__ float sW[8 * 192];   // sW[c*192 + f]
    __shared__ float sb[8];
    __shared__ float sb3[64];
    int tid = threadIdx.x;
    for (int i = tid; i < 192 * 8; i += 256) {
        int f = i >> 3, c = i & 7;
        sW[c * 192 + f] = Wl[i];
    }
    if (tid < 8)  sb[tid]  = bl[tid];
    if (tid < 64) sb3[tid] = b3[tid];
    __syncthreads();

    int node = blockIdx.x * 8 + (tid >> 5);
    int lane = tid & 31;
    if (node >= M) return;

    float dd = __ldg(dis + node);
    float f0 = __ldg(x1 + (size_t)node * 64 + lane);
    float f1 = __ldg(x1 + (size_t)node * 64 + lane + 32);
    float f2 = __ldg(x2 + (size_t)node * 64 + lane);
    float f3 = __ldg(x2 + (size_t)node * 64 + lane + 32);
    float f4 = __ldg(agg + (size_t)node * 64 + lane)      * dd + sb3[lane];
    float f5 = __ldg(agg + (size_t)node * 64 + lane + 32) * dd + sb3[lane + 32];

    float acc[8];
    #pragma unroll
    for (int c = 0; c < 8; c++) {
        const float* w = sW + c * 192;
        acc[c] = f0 * w[lane]       + f1 * w[lane + 32]
               + f2 * w[lane + 64]  + f3 * w[lane + 96]
               + f4 * w[lane + 128] + f5 * w[lane + 160];
    }
    #pragma unroll
    for (int off = 16; off; off >>= 1) {
        #pragma unroll
        for (int c = 0; c < 8; c++)
            acc[c] += __shfl_down_sync(0xffffffffu, acc[c], off);
    }
    if (lane == 0) {
        float m = -INFINITY;
        #pragma unroll
        for (int c = 0; c < 8; c++) { acc[c] += sb[c]; m = fmaxf(m, acc[c]); }
        float s = 0.f;
        #pragma unroll
        for (int c = 0; c < 8; c++) s += expf(acc[c] - m);
        float lse = logf(s) + m;
        #pragma unroll
        for (int c = 0; c < 8; c++) out[(size_t)node * 8 + c] = acc[c] - lse;
    }
}

// ---------------------------------------------------------------------------
extern "C" void kernel_launch(void* const* d_in, const int* in_sizes, int n_in,
                              void* d_out, int out_size) {
    const float* x  = (const float*)d_in[0];
    const int*   ei = (const int*)  d_in[1];
    const float* W1 = (const float*)d_in[2];
    const float* b1 = (const float*)d_in[3];
    const float* W2 = (const float*)d_in[4];
    const float* b2 = (const float*)d_in[5];
    const float* W3 = (const float*)d_in[6];
    const float* b3 = (const float*)d_in[7];
    const float* Wl = (const float*)d_in[8];
    const float* bl = (const float*)d_in[9];
    float* out = (float*)d_out;

    int N = in_sizes[0] / 128;
    int E = in_sizes[1] / 2;
    const int* src = ei;
    const int* dst = ei + E;

    float *dis, *h, *aggA, *aggB, *x1, *x2;
    cudaGetSymbolAddress((void**)&dis,  g_dis);
    cudaGetSymbolAddress((void**)&h,    g_h);
    cudaGetSymbolAddress((void**)&aggA, g_aggA);
    cudaGetSymbolAddress((void**)&aggB, g_aggB);
    cudaGetSymbolAddress((void**)&x1,   g_x1);
    cudaGetSymbolAddress((void**)&x2,   g_x2);

    int nb  = (N + 255) / 256;
    int eb  = (E + 255) / 256;
    int esb = (E + 15) / 16;
    int gb  = (N + 63) / 64;

    // normalization
    k_init_deg<<<nb, 256>>>(dis, N);
    k_count_deg<<<eb, 256>>>(dst, dis, E);
    k_rsqrt<<<nb, 256>>>(dis, N);

    // layer 1: 128 -> 64
    k_gemm<128, false><<<gb, 256>>>(x, W1, dis, nullptr, nullptr, h, aggA, N);
    k_scatter<<<esb, 256>>>(src, dst, h, aggA, E);

    // layer 2: 64 -> 64 (finalize layer-1 fused: x1 = relu(dis*aggA + b1))
    k_gemm<64, true><<<gb, 256>>>(aggA, W2, dis, b1, x1, h, aggB, N);
    k_scatter<<<esb, 256>>>(src, dst, h, aggB, E);

    // layer 3: 64 -> 64 (finalize layer-2 fused: x2 = relu(dis*aggB + b2))
    k_gemm<64, true><<<gb, 256>>>(aggB, W3, dis, b2, x2, h, aggA, N);
    k_scatter<<<esb, 256>>>(src, dst, h, aggA, E);

    // classifier (layer-3 finalize fused: x3 = dis*aggA + b3)
    k_classify<<<(N + 7) / 8, 256>>>(x1, x2, aggA, dis, b3, Wl, bl, out, N);
}

// round 3
// speedup vs baseline: 2.2046x; 1.3976x over previous
#include <cuda_runtime.h>
#include <cuda_bf16.h>
#include <math.h>

// ---------------------------------------------------------------------------
// GCN: 3x GCNConv (128->64->64->64) + concat(192) @ Wl(192x8) + log_softmax
//   h' = dis * (x @ W);  out[d] = relu?(dis[d]*(h'[d] + sum_in h'[s]) + b)
// Aggregation via destination-CSR gather (no atomics in the hot path).
// ---------------------------------------------------------------------------

#define N_NODES_MAX 50000
#define E_MAX       800000
#define FDIM 64

__device__ float g_dis [N_NODES_MAX];
__device__ float g_h   [N_NODES_MAX * FDIM];
__device__ float g_x1  [N_NODES_MAX * FDIM];
__device__ float g_x2  [N_NODES_MAX * FDIM];
__device__ float g_x3  [N_NODES_MAX * FDIM];
__device__ int   g_cnt [N_NODES_MAX];
__device__ int   g_rows[N_NODES_MAX + 1];
__device__ int   g_cur [N_NODES_MAX];
__device__ int   g_bsum[256];
__device__ int   g_csr [E_MAX];

// ---- CSR build -------------------------------------------------------------
__global__ void k_zero(int* __restrict__ cnt, int n) {
    int i = blockIdx.x * blockDim.x + threadIdx.x;
    if (i < n) cnt[i] = 0;
}

__global__ void k_hist(const int* __restrict__ dst, int* __restrict__ cnt, int e) {
    int i = blockIdx.x * blockDim.x + threadIdx.x;
    if (i < e) atomicAdd(&cnt[dst[i]], 1);
}

__device__ __forceinline__ int block_excl_scan256(int v, int tid) {
    __shared__ int ws[8];
    int lane = tid & 31, w = tid >> 5;
    int x = v;
    #pragma unroll
    for (int o = 1; o < 32; o <<= 1) {
        int y = __shfl_up_sync(0xffffffffu, x, o);
        if (lane >= o) x += y;
    }
    if (lane == 31) ws[w] = x;
    __syncthreads();
    if (w == 0) {
        int s = (lane < 8) ? ws[lane] : 0;
        #pragma unroll
        for (int o = 1; o < 8; o <<= 1) {
            int y = __shfl_up_sync(0xffffffffu, s, o);
            if (lane >= o) s += y;
        }
        if (lane < 8) ws[lane] = s;
    }
    __syncthreads();
    int base = (w > 0) ? ws[w - 1] : 0;
    return base + x - v;   // exclusive
}

// per-block sums over n+1 padded range
__global__ void k_scan1(const int* __restrict__ cnt, int* __restrict__ bsum, int n) {
    int tid = threadIdx.x;
    int i = blockIdx.x * 256 + tid;
    int v = (i < n) ? cnt[i] : 0;
    // block reduce
    #pragma unroll
    for (int o = 16; o; o >>= 1) v += __shfl_down_sync(0xffffffffu, v, o);
    __shared__ int ws[8];
    if ((tid & 31) == 0) ws[tid >> 5] = v;
    __syncthreads();
    if (tid < 8) {
        int s = ws[tid];
        #pragma unroll
        for (int o = 4; o; o >>= 1) s += __shfl_down_sync(0xffu, s, o);
        if (tid == 0) bsum[blockIdx.x] = s;
    }
}

__global__ void k_scan2(int* __restrict__ bsum, int nb) {
    int tid = threadIdx.x;
    int v = (tid < nb) ? bsum[tid] : 0;
    int e = block_excl_scan256(v, tid);
    if (tid < nb) bsum[tid] = e;
}

// row_start (exclusive), cursor copy, dis = rsqrt(cnt+1)
__global__ void k_scan3(const int* __restrict__ cnt, const int* __restrict__ bsum,
                        int* __restrict__ rows, int* __restrict__ cur,
                        float* __restrict__ dis, int n) {
    int tid = threadIdx.x;
    int i = blockIdx.x * 256 + tid;
    int v = (i < n) ? cnt[i] : 0;
    int e = block_excl_scan256(v, tid) + bsum[blockIdx.x];
    if (i <= n) rows[i] = e;
    if (i < n) {
        cur[i] = e;
        dis[i] = rsqrtf((float)(v + 1));
    }
}

__global__ void k_fill(const int* __restrict__ src, const int* __restrict__ dst,
                       int* __restrict__ cur, int* __restrict__ csr, int e) {
    int i = blockIdx.x * blockDim.x + threadIdx.x;
    if (i < e) {
        int p = atomicAdd(&cur[dst[i]], 1);
        csr[p] = src[i];
    }
}

// ---- GEMM  h = dis * (X @ W) ----------------------------------------------
// Tile: 64 rows x 64 cols per block, 256 threads, 4x4 register blocking,
// K processed in chunks of 64.
template <int K>
__global__ void __launch_bounds__(256)
k_gemm(const float* __restrict__ Xin, const float* __restrict__ W,
       const float* __restrict__ dis, float* __restrict__ h, int M) {
    constexpr int NCH = K / 64;
    __shared__ float4 Xs4[64 * 16];
    __shared__ float4 Ws4[64 * 16];

    int tid = threadIdx.x;
    int m0  = blockIdx.x * 64;
    int r4  = tid >> 4;
    int c4  = tid & 15;

    float4 acc[4];
    #pragma unroll
    for (int j = 0; j < 4; j++) acc[j] = make_float4(0.f, 0.f, 0.f, 0.f);

    const float4* W4 = (const float4*)W;

    #pragma unroll
    for (int ch = 0; ch < NCH; ch++) {
        #pragma unroll
        for (int it = 0; it < 4; it++) {
            int i = tid + it * 256;
            int r = i >> 4, c = i & 15;
            int gr = m0 + r;
            float4 v = make_float4(0.f, 0.f, 0.f, 0.f);
            if (gr < M) v = __ldg((const float4*)(Xin + (size_t)gr * K) + ch * 16 + c);
            Xs4[r * 16 + c] = v;
        }
        #pragma unroll
        for (int it = 0; it < 4; it++) {
            int i = tid + it * 256;
            Ws4[i] = __ldg(W4 + ch * 1024 + i);
        }
        __syncthreads();

        #pragma unroll
        for (int k4 = 0; k4 < 16; k4++) {
            float4 a0 = Xs4[(r4 * 4 + 0) * 16 + k4];
            float4 a1 = Xs4[(r4 * 4 + 1) * 16 + k4];
            float4 a2 = Xs4[(r4 * 4 + 2) * 16 + k4];
            float4 a3 = Xs4[(r4 * 4 + 3) * 16 + k4];
            float4 w0 = Ws4[(k4 * 4 + 0) * 16 + c4];
            float4 w1 = Ws4[(k4 * 4 + 1) * 16 + c4];
            float4 w2 = Ws4[(k4 * 4 + 2) * 16 + c4];
            float4 w3 = Ws4[(k4 * 4 + 3) * 16 + c4];
            #define ROWFMA(J, A)                                               \
                acc[J].x += A.x * w0.x + A.y * w1.x + A.z * w2.x + A.w * w3.x; \
                acc[J].y += A.x * w0.y + A.y * w1.y + A.z * w2.y + A.w * w3.y; \
                acc[J].z += A.x * w0.z + A.y * w1.z + A.z * w2.z + A.w * w3.z; \
                acc[J].w += A.x * w0.w + A.y * w1.w + A.z * w2.w + A.w * w3.w;
            ROWFMA(0, a0) ROWFMA(1, a1) ROWFMA(2, a2) ROWFMA(3, a3)
            #undef ROWFMA
        }
        if (ch + 1 < NCH) __syncthreads();
    }

    #pragma unroll
    for (int j = 0; j < 4; j++) {
        int gr = m0 + r4 * 4 + j;
        if (gr < M) {
            float dd = __ldg(dis + gr);
            float4 v = acc[j];
            v.x *= dd; v.y *= dd; v.z *= dd; v.w *= dd;
            ((float4*)(h + (size_t)gr * 64))[c4] = v;
        }
    }
}

// ---- gather: xout[g] = relu?(dis[g]*(h[g] + sum_{s in CSR row g} h[s]) + b)
template <bool RELU>
__global__ void __launch_bounds__(256)
k_gather(const int* __restrict__ rows, const int* __restrict__ csr,
         const float* __restrict__ h, const float* __restrict__ dis,
         const float* __restrict__ b, float* __restrict__ xout, int M) {
    int g = blockIdx.x * 16 + (threadIdx.x >> 4);
    if (g >= M) return;
    int lane = threadIdx.x & 15;

    int s0 = __ldg(rows + g);
    int s1 = __ldg(rows + g + 1);

    float4 acc = __ldg((const float4*)(h + (size_t)g * 64) + lane);  // self-loop
    float4 acc2 = make_float4(0.f, 0.f, 0.f, 0.f);

    int j = s0;
    for (; j + 4 <= s1; j += 4) {
        int i0 = __ldg(csr + j);
        int i1 = __ldg(csr + j + 1);
        int i2 = __ldg(csr + j + 2);
        int i3 = __ldg(csr + j + 3);
        float4 v0 = __ldg((const float4*)(h + (size_t)i0 * 64) + lane);
        float4 v1 = __ldg((const float4*)(h + (size_t)i1 * 64) + lane);
        float4 v2 = __ldg((const float4*)(h + (size_t)i2 * 64) + lane);
        float4 v3 = __ldg((const float4*)(h + (size_t)i3 * 64) + lane);
        acc.x  += v0.x + v1.x;  acc.y  += v0.y + v1.y;
        acc.z  += v0.z + v1.z;  acc.w  += v0.w + v1.w;
        acc2.x += v2.x + v3.x;  acc2.y += v2.y + v3.y;
        acc2.z += v2.z + v3.z;  acc2.w += v2.w + v3.w;
    }
    for (; j < s1; j++) {
        int i0 = __ldg(csr + j);
        float4 v0 = __ldg((const float4*)(h + (size_t)i0 * 64) + lane);
        acc.x += v0.x; acc.y += v0.y; acc.z += v0.z; acc.w += v0.w;
    }
    acc.x += acc2.x; acc.y += acc2.y; acc.z += acc2.z; acc.w += acc2.w;

    float  dd = __ldg(dis + g);
    float4 bb = __ldg((const float4*)b + lane);
    acc.x = acc.x * dd + bb.x;
    acc.y = acc.y * dd + bb.y;
    acc.z = acc.z * dd + bb.z;
    acc.w = acc.w * dd + bb.w;
    if (RELU) {
        acc.x = fmaxf(acc.x, 0.f); acc.y = fmaxf(acc.y, 0.f);
        acc.z = fmaxf(acc.z, 0.f); acc.w = fmaxf(acc.w, 0.f);
    }
    ((float4*)(xout + (size_t)g * 64))[lane] = acc;
}

// ---- classifier: log_softmax(concat(x1,x2,x3) @ Wl + bl) -------------------
__global__ void __launch_bounds__(256)
k_classify(const float* __restrict__ x1, const float* __restrict__ x2,
           const float* __restrict__ x3, const float* __restrict__ Wl,
           const float* __restrict__ bl, float* __restrict__ out, int M) {
    __shared__ float sW[8 * 192];
    __shared__ float sb[8];
    int tid = threadIdx.x;
    for (int i = tid; i < 192 * 8; i += 256) {
        int f = i >> 3, c = i & 7;
        sW[c * 192 + f] = Wl[i];
    }
    if (tid < 8) sb[tid] = bl[tid];
    __syncthreads();

    int node = blockIdx.x * 8 + (tid >> 5);
    int lane = tid & 31;
    if (node >= M) return;

    float f0 = __ldg(x1 + (size_t)node * 64 + lane);
    float f1 = __ldg(x1 + (size_t)node * 64 + lane + 32);
    float f2 = __ldg(x2 + (size_t)node * 64 + lane);
    float f3 = __ldg(x2 + (size_t)node * 64 + lane + 32);
    float f4 = __ldg(x3 + (size_t)node * 64 + lane);
    float f5 = __ldg(x3 + (size_t)node * 64 + lane + 32);

    float acc[8];
    #pragma unroll
    for (int c = 0; c < 8; c++) {
        const float* w = sW + c * 192;
        acc[c] = f0 * w[lane]       + f1 * w[lane + 32]
               + f2 * w[lane + 64]  + f3 * w[lane + 96]
               + f4 * w[lane + 128] + f5 * w[lane + 160];
    }
    #pragma unroll
    for (int off = 16; off; off >>= 1) {
        #pragma unroll
        for (int c = 0; c < 8; c++)
            acc[c] += __shfl_down_sync(0xffffffffu, acc[c], off);
    }
    if (lane == 0) {
        float m = -INFINITY;
        #pragma unroll
        for (int c = 0; c < 8; c++) { acc[c] += sb[c]; m = fmaxf(m, acc[c]); }
        float s = 0.f;
        #pragma unroll
        for (int c = 0; c < 8; c++) s += expf(acc[c] - m);
        float lse = logf(s) + m;
        #pragma unroll
        for (int c = 0; c < 8; c++) out[(size_t)node * 8 + c] = acc[c] - lse;
    }
}

// ---------------------------------------------------------------------------
extern "C" void kernel_launch(void* const* d_in, const int* in_sizes, int n_in,
                              void* d_out, int out_size) {
    const float* x  = (const float*)d_in[0];
    const int*   ei = (const int*)  d_in[1];
    const float* W1 = (const float*)d_in[2];
    const float* b1 = (const float*)d_in[3];
    const float* W2 = (const float*)d_in[4];
    const float* b2 = (const float*)d_in[5];
    const float* W3 = (const float*)d_in[6];
    const float* b3 = (const float*)d_in[7];
    const float* Wl = (const float*)d_in[8];
    const float* bl = (const float*)d_in[9];
    float* out = (float*)d_out;

    int N = in_sizes[0] / 128;
    int E = in_sizes[1] / 2;
    const int* src = ei;
    const int* dst = ei + E;

    float *dis, *h, *x1, *x2, *x3;
    int *cnt, *rows, *cur, *bsum, *csr;
    cudaGetSymbolAddress((void**)&dis,  g_dis);
    cudaGetSymbolAddress((void**)&h,    g_h);
    cudaGetSymbolAddress((void**)&x1,   g_x1);
    cudaGetSymbolAddress((void**)&x2,   g_x2);
    cudaGetSymbolAddress((void**)&x3,   g_x3);
    cudaGetSymbolAddress((void**)&cnt,  g_cnt);
    cudaGetSymbolAddress((void**)&rows, g_rows);
    cudaGetSymbolAddress((void**)&cur,  g_cur);
    cudaGetSymbolAddress((void**)&bsum, g_bsum);
    cudaGetSymbolAddress((void**)&csr,  g_csr);

    int nb   = (N + 255) / 256;
    int nb1  = (N + 1 + 255) / 256;      // covers row_start[N]
    int eb   = (E + 255) / 256;
    int gb   = (N + 63) / 64;
    int gthb = (N + 15) / 16;

    // CSR build + normalization
    k_zero <<<nb, 256>>>(cnt, N);
    k_hist <<<eb, 256>>>(dst, cnt, E);
    k_scan1<<<nb1, 256>>>(cnt, bsum, N);
    k_scan2<<<1, 256>>>(bsum, nb1);
    k_scan3<<<nb1, 256>>>(cnt, bsum, rows, cur, dis, N);
    k_fill <<<eb, 256>>>(src, dst, cur, csr, E);

    // layer 1: 128 -> 64, relu
    k_gemm<128><<<gb, 256>>>(x, W1, dis, h, N);
    k_gather<true><<<gthb, 256>>>(rows, csr, h, dis, b1, x1, N);

    // layer 2: 64 -> 64, relu
    k_gemm<64><<<gb, 256>>>(x1, W2, dis, h, N);
    k_gather<true><<<gthb, 256>>>(rows, csr, h, dis, b2, x2, N);

    // layer 3: 64 -> 64, no relu
    k_gemm<64><<<gb, 256>>>(x2, W3, dis, h, N);
    k_gather<false><<<gthb, 256>>>(rows, csr, h, dis, b3, x3, N);

    // classifier
    k_classify<<<(N + 7) / 8, 256>>>(x1, x2, x3, Wl, bl, out, N);
}

// round 4
// speedup vs baseline: 2.3464x; 1.0643x over previous
#include <cuda_runtime.h>
#include <cuda_bf16.h>
#include <math.h>

// ---------------------------------------------------------------------------
// GCN: 3x GCNConv (128->64->64->64) + concat(192) @ Wl(192x8) + log_softmax
//   h' = dis * (x @ W);  out[d] = relu?(dis[d]*(h'[d] + sum_in h'[s]) + b)
// Aggregation via destination-CSR gather (no atomics in the hot path).
// ---------------------------------------------------------------------------

#define N_NODES_MAX 50000
#define E_MAX       800000
#define FDIM 64

__device__ float g_dis [N_NODES_MAX];
__device__ float g_h   [N_NODES_MAX * FDIM];
__device__ float g_x1  [N_NODES_MAX * FDIM];
__device__ float g_x2  [N_NODES_MAX * FDIM];
__device__ float g_x3  [N_NODES_MAX * FDIM];
__device__ int   g_cnt [N_NODES_MAX];         // zeroed at end of each call
__device__ int   g_rows[N_NODES_MAX + 1];
__device__ int   g_cur [N_NODES_MAX];
__device__ int   g_bsum[256];
__device__ int   g_csr [E_MAX];

// ---- CSR build -------------------------------------------------------------
__global__ void k_hist(const int* __restrict__ dst, int* __restrict__ cnt, int e) {
    int i = blockIdx.x * blockDim.x + threadIdx.x;
    if (i < e) atomicAdd(&cnt[dst[i]], 1);
}

__device__ __forceinline__ int block_excl_scan256(int v, int tid) {
    __shared__ int ws[8];
    int lane = tid & 31, w = tid >> 5;
    int x = v;
    #pragma unroll
    for (int o = 1; o < 32; o <<= 1) {
        int y = __shfl_up_sync(0xffffffffu, x, o);
        if (lane >= o) x += y;
    }
    if (lane == 31) ws[w] = x;
    __syncthreads();
    if (w == 0) {
        int s = (lane < 8) ? ws[lane] : 0;
        #pragma unroll
        for (int o = 1; o < 8; o <<= 1) {
            int y = __shfl_up_sync(0xffffffffu, s, o);
            if (lane >= o) s += y;
        }
        if (lane < 8) ws[lane] = s;
    }
    __syncthreads();
    int base = (w > 0) ? ws[w - 1] : 0;
    return base + x - v;   // exclusive
}

// per-block sums
__global__ void k_scan1(const int* __restrict__ cnt, int* __restrict__ bsum, int n) {
    int tid = threadIdx.x;
    int i = blockIdx.x * 256 + tid;
    int v = (i < n) ? cnt[i] : 0;
    #pragma unroll
    for (int o = 16; o; o >>= 1) v += __shfl_down_sync(0xffffffffu, v, o);
    __shared__ int ws[8];
    if ((tid & 31) == 0) ws[tid >> 5] = v;
    __syncthreads();
    if (tid < 8) {
        int s = ws[tid];
        #pragma unroll
        for (int o = 4; o; o >>= 1) s += __shfl_down_sync(0xffu, s, o);
        if (tid == 0) bsum[blockIdx.x] = s;
    }
}

// fused: per-block base from bsum prefix + local scan + rows/cur/dis + cnt:=0
__global__ void k_scan3(int* __restrict__ cnt, const int* __restrict__ bsum,
                        int* __restrict__ rows, int* __restrict__ cur,
                        float* __restrict__ dis, int n) {
    int tid = threadIdx.x;
    int bid = blockIdx.x;
    __shared__ int wsb[8];
    __shared__ int sbase;

    int bv = (tid < bid) ? bsum[tid] : 0;       // bid < 256 always
    #pragma unroll
    for (int o = 16; o; o >>= 1) bv += __shfl_down_sync(0xffffffffu, bv, o);
    if ((tid & 31) == 0) wsb[tid >> 5] = bv;
    __syncthreads();
    if (tid == 0) {
        int s = 0;
        #pragma unroll
        for (int w = 0; w < 8; w++) s += wsb[w];
        sbase = s;
    }
    __syncthreads();

    int i = bid * 256 + tid;
    int v = (i < n) ? cnt[i] : 0;
    int e = block_excl_scan256(v, tid) + sbase;
    if (i <= n) rows[i] = e;
    if (i < n) {
        cur[i] = e;
        dis[i] = rsqrtf((float)(v + 1));
        cnt[i] = 0;                              // ready for next call
    }
}

__global__ void k_fill(const int* __restrict__ src, const int* __restrict__ dst,
                       int* __restrict__ cur, int* __restrict__ csr, int e) {
    int i = blockIdx.x * blockDim.x + threadIdx.x;
    if (i < e) {
        int p = atomicAdd(&cur[dst[i]], 1);
        csr[p] = src[i];
    }
}

// ---- GEMM  h = dis * (X @ W) ----------------------------------------------
// 128 threads/block, tile 128 rows x 64 cols, 8x8 per thread, K chunks of 32.
// A read as scalar broadcasts (row-major smem, pitch 33), W as float4 pairs.
template <int K>
__global__ void __launch_bounds__(128, 4)
k_gemm(const float* __restrict__ Xin, const float* __restrict__ W,
       const float* __restrict__ dis, float* __restrict__ h, int M) {
    constexpr int NCH = K / 32;
    __shared__ float  Xs [128 * 33];
    __shared__ float4 Ws4[32 * 16];

    int tid = threadIdx.x;
    int tx  = tid & 7;     // col group: cols tx*4..+3 and 32+tx*4..+3
    int ty  = tid >> 3;    // row group: rows ty*8..+7
    int m0  = blockIdx.x * 128;

    float acc[8][8];
    #pragma unroll
    for (int j = 0; j < 8; j++)
        #pragma unroll
        for (int i = 0; i < 8; i++) acc[j][i] = 0.f;

    const float4* W4 = (const float4*)W;

    #pragma unroll
    for (int ch = 0; ch < NCH; ch++) {
        // A chunk: 128 rows x 8 float4
        #pragma unroll
        for (int it = 0; it < 8; it++) {
            int i = tid + it * 128;
            int r = i >> 3, c = i & 7;
            int gr = m0 + r;
            float4 v = make_float4(0.f, 0.f, 0.f, 0.f);
            if (gr < M) v = __ldg((const float4*)(Xin + (size_t)gr * K) + ch * 8 + c);
            float* p = Xs + r * 33 + c * 4;
            p[0] = v.x; p[1] = v.y; p[2] = v.z; p[3] = v.w;
        }
        // W chunk: 32 k x 16 float4
        #pragma unroll
        for (int it = 0; it < 4; it++) {
            int i = tid + it * 128;
            Ws4[i] = __ldg(W4 + ch * 512 + i);
        }
        __syncthreads();

        #pragma unroll 8
        for (int k = 0; k < 32; k++) {
            float a[8];
            #pragma unroll
            for (int j = 0; j < 8; j++) a[j] = Xs[(ty * 8 + j) * 33 + k];
            float4 w0 = Ws4[k * 16 + tx];
            float4 w1 = Ws4[k * 16 + 8 + tx];
            #pragma unroll
            for (int j = 0; j < 8; j++) {
                acc[j][0] += a[j] * w0.x;
                acc[j][1] += a[j] * w0.y;
                acc[j][2] += a[j] * w0.z;
                acc[j][3] += a[j] * w0.w;
                acc[j][4] += a[j] * w1.x;
                acc[j][5] += a[j] * w1.y;
                acc[j][6] += a[j] * w1.z;
                acc[j][7] += a[j] * w1.w;
            }
        }
        if (ch + 1 < NCH) __syncthreads();
    }

    #pragma unroll
    for (int j = 0; j < 8; j++) {
        int gr = m0 + ty * 8 + j;
        if (gr < M) {
            float dd = __ldg(dis + gr);
            float4 o0 = make_float4(acc[j][0] * dd, acc[j][1] * dd,
                                    acc[j][2] * dd, acc[j][3] * dd);
            float4 o1 = make_float4(acc[j][4] * dd, acc[j][5] * dd,
                                    acc[j][6] * dd, acc[j][7] * dd);
            ((float4*)(h + (size_t)gr * 64))[tx]     = o0;
            ((float4*)(h + (size_t)gr * 64))[8 + tx] = o1;
        }
    }
}

// ---- gather: xout[g] = relu?(dis[g]*(h[g] + sum_{s in CSR row g} h[s]) + b)
template <bool RELU>
__global__ void __launch_bounds__(256)
k_gather(const int* __restrict__ rows, const int* __restrict__ csr,
         const float* __restrict__ h, const float* __restrict__ dis,
         const float* __restrict__ b, float* __restrict__ xout, int M) {
    int g = blockIdx.x * 16 + (threadIdx.x >> 4);
    if (g >= M) return;
    int lane = threadIdx.x & 15;

    int s0 = __ldg(rows + g);
    int s1 = __ldg(rows + g + 1);

    float4 acc = __ldg((const float4*)(h + (size_t)g * 64) + lane);  // self-loop
    float4 acc2 = make_float4(0.f, 0.f, 0.f, 0.f);

    int j = s0;
    for (; j + 4 <= s1; j += 4) {
        int i0 = __ldg(csr + j);
        int i1 = __ldg(csr + j + 1);
        int i2 = __ldg(csr + j + 2);
        int i3 = __ldg(csr + j + 3);
        float4 v0 = __ldg((const float4*)(h + (size_t)i0 * 64) + lane);
        float4 v1 = __ldg((const float4*)(h + (size_t)i1 * 64) + lane);
        float4 v2 = __ldg((const float4*)(h + (size_t)i2 * 64) + lane);
        float4 v3 = __ldg((const float4*)(h + (size_t)i3 * 64) + lane);
        acc.x  += v0.x + v1.x;  acc.y  += v0.y + v1.y;
        acc.z  += v0.z + v1.z;  acc.w  += v0.w + v1.w;
        acc2.x += v2.x + v3.x;  acc2.y += v2.y + v3.y;
        acc2.z += v2.z + v3.z;  acc2.w += v2.w + v3.w;
    }
    for (; j < s1; j++) {
        int i0 = __ldg(csr + j);
        float4 v0 = __ldg((const float4*)(h + (size_t)i0 * 64) + lane);
        acc.x += v0.x; acc.y += v0.y; acc.z += v0.z; acc.w += v0.w;
    }
    acc.x += acc2.x; acc.y += acc2.y; acc.z += acc2.z; acc.w += acc2.w;

    float  dd = __ldg(dis + g);
    float4 bb = __ldg((const float4*)b + lane);
    acc.x = acc.x * dd + bb.x;
    acc.y = acc.y * dd + bb.y;
    acc.z = acc.z * dd + bb.z;
    acc.w = acc.w * dd + bb.w;
    if (RELU) {
        acc.x = fmaxf(acc.x, 0.f); acc.y = fmaxf(acc.y, 0.f);
        acc.z = fmaxf(acc.z, 0.f); acc.w = fmaxf(acc.w, 0.f);
    }
    ((float4*)(xout + (size_t)g * 64))[lane] = acc;
}

// ---- classifier: log_softmax(concat(x1,x2,x3) @ Wl + bl) -------------------
__global__ void __launch_bounds__(256)
k_classify(const float* __restrict__ x1, const float* __restrict__ x2,
           const float* __restrict__ x3, const float* __restrict__ Wl,
           const float* __restrict__ bl, float* __restrict__ out, int M) {
    __shared__ float sW[8 * 192];
    __shared__ float sb[8];
    int tid = threadIdx.x;
    for (int i = tid; i < 192 * 8; i += 256) {
        int f = i >> 3, c = i & 7;
        sW[c * 192 + f] = Wl[i];
    }
    if (tid < 8) sb[tid] = bl[tid];
    __syncthreads();

    int node = blockIdx.x * 8 + (tid >> 5);
    int lane = tid & 31;
    if (node >= M) return;

    float f0 = __ldg(x1 + (size_t)node * 64 + lane);
    float f1 = __ldg(x1 + (size_t)node * 64 + lane + 32);
    float f2 = __ldg(x2 + (size_t)node * 64 + lane);
    float f3 = __ldg(x2 + (size_t)node * 64 + lane + 32);
    float f4 = __ldg(x3 + (size_t)node * 64 + lane);
    float f5 = __ldg(x3 + (size_t)node * 64 + lane + 32);

    float acc[8];
    #pragma unroll
    for (int c = 0; c < 8; c++) {
        const float* w = sW + c * 192;
        acc[c] = f0 * w[lane]       + f1 * w[lane + 32]
               + f2 * w[lane + 64]  + f3 * w[lane + 96]
               + f4 * w[lane + 128] + f5 * w[lane + 160];
    }
    #pragma unroll
    for (int off = 16; off; off >>= 1) {
        #pragma unroll
        for (int c = 0; c < 8; c++)
            acc[c] += __shfl_down_sync(0xffffffffu, acc[c], off);
    }
    if (lane == 0) {
        float m = -INFINITY;
        #pragma unroll
        for (int c = 0; c < 8; c++) { acc[c] += sb[c]; m = fmaxf(m, acc[c]); }
        float s = 0.f;
        #pragma unroll
        for (int c = 0; c < 8; c++) s += expf(acc[c] - m);
        float lse = logf(s) + m;
        #pragma unroll
        for (int c = 0; c < 8; c++) out[(size_t)node * 8 + c] = acc[c] - lse;
    }
}

// ---------------------------------------------------------------------------
extern "C" void kernel_launch(void* const* d_in, const int* in_sizes, int n_in,
                              void* d_out, int out_size) {
    const float* x  = (const float*)d_in[0];
    const int*   ei = (const int*)  d_in[1];
    const float* W1 = (const float*)d_in[2];
    const float* b1 = (const float*)d_in[3];
    const float* W2 = (const float*)d_in[4];
    const float* b2 = (const float*)d_in[5];
    const float* W3 = (const float*)d_in[6];
    const float* b3 = (const float*)d_in[7];
    const float* Wl = (const float*)d_in[8];
    const float* bl = (const float*)d_in[9];
    float* out = (float*)d_out;

    int N = in_sizes[0] / 128;
    int E = in_sizes[1] / 2;
    const int* src = ei;
    const int* dst = ei + E;

    float *dis, *h, *x1, *x2, *x3;
    int *cnt, *rows, *cur, *bsum, *csr;
    cudaGetSymbolAddress((void**)&dis,  g_dis);
    cudaGetSymbolAddress((void**)&h,    g_h);
    cudaGetSymbolAddress((void**)&x1,   g_x1);
    cudaGetSymbolAddress((void**)&x2,   g_x2);
    cudaGetSymbolAddress((void**)&x3,   g_x3);
    cudaGetSymbolAddress((void**)&cnt,  g_cnt);
    cudaGetSymbolAddress((void**)&rows, g_rows);
    cudaGetSymbolAddress((void**)&cur,  g_cur);
    cudaGetSymbolAddress((void**)&bsum, g_bsum);
    cudaGetSymbolAddress((void**)&csr,  g_csr);

    int nb1  = (N + 1 + 255) / 256;      // covers row_start[N]
    int eb   = (E + 255) / 256;
    int gb   = (N + 127) / 128;
    int gthb = (N + 15) / 16;

    // CSR build + normalization (cnt arrives zeroed; re-zeroed in k_scan3)
    k_hist <<<eb, 256>>>(dst, cnt, E);
    k_scan1<<<nb1, 256>>>(cnt, bsum, N);
    k_scan3<<<nb1, 256>>>(cnt, bsum, rows, cur, dis, N);
    k_fill <<<eb, 256>>>(src, dst, cur, csr, E);

    // layer 1: 128 -> 64, relu
    k_gemm<128><<<gb, 128>>>(x, W1, dis, h, N);
    k_gather<true><<<gthb, 256>>>(rows, csr, h, dis, b1, x1, N);

    // layer 2: 64 -> 64, relu
    k_gemm<64><<<gb, 128>>>(x1, W2, dis, h, N);
    k_gather<true><<<gthb, 256>>>(rows, csr, h, dis, b2, x2, N);

    // layer 3: 64 -> 64, no relu
    k_gemm<64><<<gb, 128>>>(x2, W3, dis, h, N);
    k_gather<false><<<gthb, 256>>>(rows, csr, h, dis, b3, x3, N);

    // classifier
    k_classify<<<(N + 7) / 8, 256>>>(x1, x2, x3, Wl, bl, out, N);
}

// round 5
// speedup vs baseline: 2.6454x; 1.1274x over previous
#include <cuda_runtime.h>
#include <cuda_fp16.h>
#include <math.h>

// ---------------------------------------------------------------------------
// GCN: 3x GCNConv (128->64->64->64) + concat(192) @ Wl(192x8) + log_softmax
//   h' = dis * (x @ W)  [stored fp16];  out[d] = relu?(dis[d]*(sum h') + b)
// Destination-CSR gather (atomic-free fill via per-edge rank), fp32 accumulate.
// Layer-3 gather fused with the classifier.
// ---------------------------------------------------------------------------

#define N_NODES_MAX 50000
#define E_MAX       800000
#define FDIM 64

__device__ float  g_dis [N_NODES_MAX];
__device__ __half g_h   [N_NODES_MAX * FDIM];
__device__ float  g_x1  [N_NODES_MAX * FDIM];
__device__ float  g_x2  [N_NODES_MAX * FDIM];
__device__ int    g_cnt [N_NODES_MAX];         // zeroed at end of each call
__device__ int    g_rows[N_NODES_MAX + 1];
__device__ int    g_rank[E_MAX];
__device__ int    g_bsum[256];
__device__ int    g_csr [E_MAX];

// ---- CSR build -------------------------------------------------------------
__global__ void k_hist(const int* __restrict__ dst, int* __restrict__ cnt,
                       int* __restrict__ rank, int e) {
    int i = blockIdx.x * blockDim.x + threadIdx.x;
    if (i < e) rank[i] = atomicAdd(&cnt[dst[i]], 1);
}

__device__ __forceinline__ int block_excl_scan256(int v, int tid) {
    __shared__ int ws[8];
    int lane = tid & 31, w = tid >> 5;
    int x = v;
    #pragma unroll
    for (int o = 1; o < 32; o <<= 1) {
        int y = __shfl_up_sync(0xffffffffu, x, o);
        if (lane >= o) x += y;
    }
    if (lane == 31) ws[w] = x;
    __syncthreads();
    if (w == 0) {
        int s = (lane < 8) ? ws[lane] : 0;
        #pragma unroll
        for (int o = 1; o < 8; o <<= 1) {
            int y = __shfl_up_sync(0xffffffffu, s, o);
            if (lane >= o) s += y;
        }
        if (lane < 8) ws[lane] = s;
    }
    __syncthreads();
    int base = (w > 0) ? ws[w - 1] : 0;
    return base + x - v;   // exclusive
}

// per-block sums
__global__ void k_scan1(const int* __restrict__ cnt, int* __restrict__ bsum, int n) {
    int tid = threadIdx.x;
    int i = blockIdx.x * 256 + tid;
    int v = (i < n) ? cnt[i] : 0;
    #pragma unroll
    for (int o = 16; o; o >>= 1) v += __shfl_down_sync(0xffffffffu, v, o);
    __shared__ int ws[8];
    if ((tid & 31) == 0) ws[tid >> 5] = v;
    __syncthreads();
    if (tid < 8) {
        int s = ws[tid];
        #pragma unroll
        for (int o = 4; o; o >>= 1) s += __shfl_down_sync(0xffu, s, o);
        if (tid == 0) bsum[blockIdx.x] = s;
    }
}

// fused: per-block base from bsum prefix + local scan + rows/dis + cnt:=0
__global__ void k_scan3(int* __restrict__ cnt, const int* __restrict__ bsum,
                        int* __restrict__ rows, float* __restrict__ dis, int n) {
    int tid = threadIdx.x;
    int bid = blockIdx.x;
    __shared__ int wsb[8];
    __shared__ int sbase;

    int bv = (tid < bid) ? bsum[tid] : 0;       // bid < 256 always
    #pragma unroll
    for (int o = 16; o; o >>= 1) bv += __shfl_down_sync(0xffffffffu, bv, o);
    if ((tid & 31) == 0) wsb[tid >> 5] = bv;
    __syncthreads();
    if (tid == 0) {
        int s = 0;
        #pragma unroll
        for (int w = 0; w < 8; w++) s += wsb[w];
        sbase = s;
    }
    __syncthreads();

    int i = bid * 256 + tid;
    int v = (i < n) ? cnt[i] : 0;
    int e = block_excl_scan256(v, tid) + sbase;
    if (i <= n) rows[i] = e;
    if (i < n) {
        dis[i] = rsqrtf((float)(v + 1));
        cnt[i] = 0;                              // ready for next call
    }
}

// atomic-free fill: csr[rows[dst] + rank] = src
__global__ void k_fill(const int* __restrict__ src, const int* __restrict__ dst,
                       const int* __restrict__ rows, const int* __restrict__ rank,
                       int* __restrict__ csr, int e) {
    int i = blockIdx.x * blockDim.x + threadIdx.x;
    if (i < e) csr[__ldg(rows + dst[i]) + rank[i]] = src[i];
}

// ---- GEMM  h = fp16( dis * (X @ W) ) ---------------------------------------
// 128 threads/block, tile 128 rows x 64 cols, 8x8 per thread, K chunks of 32.
template <int K>
__global__ void __launch_bounds__(128, 4)
k_gemm(const float* __restrict__ Xin, const float* __restrict__ W,
       const float* __restrict__ dis, __half* __restrict__ h, int M) {
    constexpr int NCH = K / 32;
    __shared__ float  Xs [128 * 33];
    __shared__ float4 Ws4[32 * 16];

    int tid = threadIdx.x;
    int tx  = tid & 7;
    int ty  = tid >> 3;
    int m0  = blockIdx.x * 128;

    float acc[8][8];
    #pragma unroll
    for (int j = 0; j < 8; j++)
        #pragma unroll
        for (int i = 0; i < 8; i++) acc[j][i] = 0.f;

    const float4* W4 = (const float4*)W;

    #pragma unroll
    for (int ch = 0; ch < NCH; ch++) {
        #pragma unroll
        for (int it = 0; it < 8; it++) {
            int i = tid + it * 128;
            int r = i >> 3, c = i & 7;
            int gr = m0 + r;
            float4 v = make_float4(0.f, 0.f, 0.f, 0.f);
            if (gr < M) v = __ldg((const float4*)(Xin + (size_t)gr * K) + ch * 8 + c);
            float* p = Xs + r * 33 + c * 4;
            p[0] = v.x; p[1] = v.y; p[2] = v.z; p[3] = v.w;
        }
        #pragma unroll
        for (int it = 0; it < 4; it++) {
            int i = tid + it * 128;
            Ws4[i] = __ldg(W4 + ch * 512 + i);
        }
        __syncthreads();

        #pragma unroll 8
        for (int k = 0; k < 32; k++) {
            float a[8];
            #pragma unroll
            for (int j = 0; j < 8; j++) a[j] = Xs[(ty * 8 + j) * 33 + k];
            float4 w0 = Ws4[k * 16 + tx];
            float4 w1 = Ws4[k * 16 + 8 + tx];
            #pragma unroll
            for (int j = 0; j < 8; j++) {
                acc[j][0] += a[j] * w0.x;
                acc[j][1] += a[j] * w0.y;
                acc[j][2] += a[j] * w0.z;
                acc[j][3] += a[j] * w0.w;
                acc[j][4] += a[j] * w1.x;
                acc[j][5] += a[j] * w1.y;
                acc[j][6] += a[j] * w1.z;
                acc[j][7] += a[j] * w1.w;
            }
        }
        if (ch + 1 < NCH) __syncthreads();
    }

    #pragma unroll
    for (int j = 0; j < 8; j++) {
        int gr = m0 + ty * 8 + j;
        if (gr < M) {
            float dd = __ldg(dis + gr);
            __half2 h0 = __floats2half2_rn(acc[j][0] * dd, acc[j][1] * dd);
            __half2 h1 = __floats2half2_rn(acc[j][2] * dd, acc[j][3] * dd);
            __half2 h2 = __floats2half2_rn(acc[j][4] * dd, acc[j][5] * dd);
            __half2 h3 = __floats2half2_rn(acc[j][6] * dd, acc[j][7] * dd);
            uint2 u0, u1;
            u0.x = *reinterpret_cast<unsigned*>(&h0);
            u0.y = *reinterpret_cast<unsigned*>(&h1);
            u1.x = *reinterpret_cast<unsigned*>(&h2);
            u1.y = *reinterpret_cast<unsigned*>(&h3);
            uint2* hp = (uint2*)(h + (size_t)gr * 64);
            hp[tx]     = u0;
            hp[8 + tx] = u1;
        }
    }
}

// ---- fp16 row read helper --------------------------------------------------
__device__ __forceinline__ float4 ld_h4(const __half* __restrict__ h,
                                        int node, int lane) {
    uint2 r = __ldg((const uint2*)(h + (size_t)node * 64) + lane);
    __half2 ha = *reinterpret_cast<__half2*>(&r.x);
    __half2 hb = *reinterpret_cast<__half2*>(&r.y);
    float2 fa = __half22float2(ha);
    float2 fb = __half22float2(hb);
    return make_float4(fa.x, fa.y, fb.x, fb.y);
}

__device__ __forceinline__ float4 gather_row(const int* __restrict__ rows,
                                             const int* __restrict__ csr,
                                             const __half* __restrict__ h,
                                             int g, int lane) {
    int s0 = __ldg(rows + g);
    int s1 = __ldg(rows + g + 1);
    float4 acc  = ld_h4(h, g, lane);   // self-loop
    float4 acc2 = make_float4(0.f, 0.f, 0.f, 0.f);
    int j = s0;
    for (; j + 4 <= s1; j += 4) {
        int i0 = __ldg(csr + j);
        int i1 = __ldg(csr + j + 1);
        int i2 = __ldg(csr + j + 2);
        int i3 = __ldg(csr + j + 3);
        float4 v0 = ld_h4(h, i0, lane);
        float4 v1 = ld_h4(h, i1, lane);
        float4 v2 = ld_h4(h, i2, lane);
        float4 v3 = ld_h4(h, i3, lane);
        acc.x  += v0.x + v1.x;  acc.y  += v0.y + v1.y;
        acc.z  += v0.z + v1.z;  acc.w  += v0.w + v1.w;
        acc2.x += v2.x + v3.x;  acc2.y += v2.y + v3.y;
        acc2.z += v2.z + v3.z;  acc2.w += v2.w + v3.w;
    }
    for (; j < s1; j++) {
        float4 v0 = ld_h4(h, __ldg(csr + j), lane);
        acc.x += v0.x; acc.y += v0.y; acc.z += v0.z; acc.w += v0.w;
    }
    acc.x += acc2.x; acc.y += acc2.y; acc.z += acc2.z; acc.w += acc2.w;
    return acc;
}

// ---- gather (layers 1,2): xout[g] = relu(dis[g]*sum + b) -------------------
__global__ void __launch_bounds__(256)
k_gather(const int* __restrict__ rows, const int* __restrict__ csr,
         const __half* __restrict__ h, const float* __restrict__ dis,
         const float* __restrict__ b, float* __restrict__ xout, int M) {
    int g = blockIdx.x * 16 + (threadIdx.x >> 4);
    if (g >= M) return;
    int lane = threadIdx.x & 15;

    float4 acc = gather_row(rows, csr, h, g, lane);
    float  dd = __ldg(dis + g);
    float4 bb = __ldg((const float4*)b + lane);
    acc.x = fmaxf(acc.x * dd + bb.x, 0.f);
    acc.y = fmaxf(acc.y * dd + bb.y, 0.f);
    acc.z = fmaxf(acc.z * dd + bb.z, 0.f);
    acc.w = fmaxf(acc.w * dd + bb.w, 0.f);
    ((float4*)(xout + (size_t)g * 64))[lane] = acc;
}

// ---- layer-3 gather fused with classifier ----------------------------------
// x3 = dis*sum + b3 (no relu, kept in registers);
// out = log_softmax(concat(x1,x2,x3) @ Wl + bl)
__global__ void __launch_bounds__(256)
k_gather_classify(const int* __restrict__ rows, const int* __restrict__ csr,
                  const __half* __restrict__ h, const float* __restrict__ dis,
                  const float* __restrict__ b3,
                  const float* __restrict__ x1, const float* __restrict__ x2,
                  const float* __restrict__ Wl, const float* __restrict__ bl,
                  float* __restrict__ out, int M) {
    __shared__ float sW[8 * 192];   // sW[c*192 + f]
    __shared__ float sb[8];
    int tid = threadIdx.x;
    for (int i = tid; i < 192 * 8; i += 256) {
        int f = i >> 3, c = i & 7;
        sW[c * 192 + f] = Wl[i];
    }
    if (tid < 8) sb[tid] = bl[tid];
    __syncthreads();

    int g = blockIdx.x * 16 + (tid >> 4);
    if (g >= M) return;
    int lane = tid & 15;

    float4 acc = gather_row(rows, csr, h, g, lane);
    float  dd = __ldg(dis + g);
    float4 bb = __ldg((const float4*)b3 + lane);
    float x3v[4];
    x3v[0] = acc.x * dd + bb.x;
    x3v[1] = acc.y * dd + bb.y;
    x3v[2] = acc.z * dd + bb.z;
    x3v[3] = acc.w * dd + bb.w;

    float4 v1 = __ldg((const float4*)(x1 + (size_t)g * 64) + lane);
    float4 v2 = __ldg((const float4*)(x2 + (size_t)g * 64) + lane);
    float x1v[4] = {v1.x, v1.y, v1.z, v1.w};
    float x2v[4] = {v2.x, v2.y, v2.z, v2.w};

    unsigned mask = 0xFFFFu << (tid & 0x10);   // this thread's half-warp

    float lg[8];
    #pragma unroll
    for (int c = 0; c < 8; c++) {
        const float* w = sW + c * 192 + 4 * lane;
        float s = 0.f;
        #pragma unroll
        for (int j = 0; j < 4; j++) {
            s += x1v[j] * w[j];
            s += x2v[j] * w[64 + j];
            s += x3v[j] * w[128 + j];
        }
        #pragma unroll
        for (int o = 8; o; o >>= 1)
            s += __shfl_xor_sync(mask, s, o, 16);
        lg[c] = s;
    }

    if (lane == 0) {
        float m = -INFINITY;
        #pragma unroll
        for (int c = 0; c < 8; c++) { lg[c] += sb[c]; m = fmaxf(m, lg[c]); }
        float s = 0.f;
        #pragma unroll
        for (int c = 0; c < 8; c++) s += expf(lg[c] - m);
        float lse = logf(s) + m;
        #pragma unroll
        for (int c = 0; c < 8; c++) out[(size_t)g * 8 + c] = lg[c] - lse;
    }
}

// ---------------------------------------------------------------------------
extern "C" void kernel_launch(void* const* d_in, const int* in_sizes, int n_in,
                              void* d_out, int out_size) {
    const float* x  = (const float*)d_in[0];
    const int*   ei = (const int*)  d_in[1];
    const float* W1 = (const float*)d_in[2];
    const float* b1 = (const float*)d_in[3];
    const float* W2 = (const float*)d_in[4];
    const float* b2 = (const float*)d_in[5];
    const float* W3 = (const float*)d_in[6];
    const float* b3 = (const float*)d_in[7];
    const float* Wl = (const float*)d_in[8];
    const float* bl = (const float*)d_in[9];
    float* out = (float*)d_out;

    int N = in_sizes[0] / 128;
    int E = in_sizes[1] / 2;
    const int* src = ei;
    const int* dst = ei + E;

    float *dis, *x1, *x2;
    __half* h;
    int *cnt, *rows, *rank, *bsum, *csr;
    cudaGetSymbolAddress((void**)&dis,  g_dis);
    cudaGetSymbolAddress((void**)&h,    g_h);
    cudaGetSymbolAddress((void**)&x1,   g_x1);
    cudaGetSymbolAddress((void**)&x2,   g_x2);
    cudaGetSymbolAddress((void**)&cnt,  g_cnt);
    cudaGetSymbolAddress((void**)&rows, g_rows);
    cudaGetSymbolAddress((void**)&rank, g_rank);
    cudaGetSymbolAddress((void**)&bsum, g_bsum);
    cudaGetSymbolAddress((void**)&csr,  g_csr);

    int nb1  = (N + 1 + 255) / 256;      // covers row_start[N]
    int eb   = (E + 255) / 256;
    int gb   = (N + 127) / 128;
    int gthb = (N + 15) / 16;

    // CSR build + normalization (cnt arrives zeroed; re-zeroed in k_scan3)
    k_hist <<<eb, 256>>>(dst, cnt, rank, E);
    k_scan1<<<nb1, 256>>>(cnt, bsum, N);
    k_scan3<<<nb1, 256>>>(cnt, bsum, rows, dis, N);
    k_fill <<<eb, 256>>>(src, dst, rows, rank, csr, E);

    // layer 1: 128 -> 64, relu
    k_gemm<128><<<gb, 128>>>(x, W1, dis, h, N);
    k_gather<<<gthb, 256>>>(rows, csr, h, dis, b1, x1, N);

    // layer 2: 64 -> 64, relu
    k_gemm<64><<<gb, 128>>>(x1, W2, dis, h, N);
    k_gather<<<gthb, 256>>>(rows, csr, h, dis, b2, x2, N);

    // layer 3: 64 -> 64 + classifier (fused)
    k_gemm<64><<<gb, 128>>>(x2, W3, dis, h, N);
    k_gather_classify<<<gthb, 256>>>(rows, csr, h, dis, b3, x1, x2,
                                     Wl, bl, out, N);
}

// round 6
// speedup vs baseline: 2.6483x; 1.0011x over previous
#include <cuda_runtime.h>
#include <cuda_fp16.h>
#include <math.h>

// ---------------------------------------------------------------------------
// GCN: 3x GCNConv (128->64->64->64) + concat(192) @ Wl(192x8) + log_softmax
// Destination-CSR gather (atomic-free fill), fp16 message buffer, fp32 accum.
// CSR build overlapped with layer-1 GEMM via forked capture stream:
//   layer-1 h is UNSCALED; gather-1 applies dis[src] per edge.
// ---------------------------------------------------------------------------

#define N_NODES_MAX 50000
#define E_MAX       800000
#define FDIM 64

__device__ float  g_dis [N_NODES_MAX];
__device__ __half g_h   [N_NODES_MAX * FDIM];
__device__ float  g_x1  [N_NODES_MAX * FDIM];
__device__ float  g_x2  [N_NODES_MAX * FDIM];
__device__ int    g_cnt [N_NODES_MAX];         // zeroed at end of each call
__device__ int    g_rows[N_NODES_MAX + 1];
__device__ int    g_rank[E_MAX];
__device__ int    g_bsum[256];
__device__ int    g_csr [E_MAX];

// ---- CSR build (4 edges per thread, MLP=4) ---------------------------------
__global__ void k_hist(const int* __restrict__ dst, int* __restrict__ cnt,
                       int* __restrict__ rank, int e) {
    int i = (blockIdx.x * blockDim.x + threadIdx.x) * 4;
    if (i + 3 < e) {
        int4 d = *(const int4*)(dst + i);
        int4 r;
        r.x = atomicAdd(&cnt[d.x], 1);
        r.y = atomicAdd(&cnt[d.y], 1);
        r.z = atomicAdd(&cnt[d.z], 1);
        r.w = atomicAdd(&cnt[d.w], 1);
        *(int4*)(rank + i) = r;
    } else {
        for (; i < e; i++) rank[i] = atomicAdd(&cnt[dst[i]], 1);
    }
}

__device__ __forceinline__ int block_excl_scan256(int v, int tid) {
    __shared__ int ws[8];
    int lane = tid & 31, w = tid >> 5;
    int x = v;
    #pragma unroll
    for (int o = 1; o < 32; o <<= 1) {
        int y = __shfl_up_sync(0xffffffffu, x, o);
        if (lane >= o) x += y;
    }
    if (lane == 31) ws[w] = x;
    __syncthreads();
    if (w == 0) {
        int s = (lane < 8) ? ws[lane] : 0;
        #pragma unroll
        for (int o = 1; o < 8; o <<= 1) {
            int y = __shfl_up_sync(0xffffffffu, s, o);
            if (lane >= o) s += y;
        }
        if (lane < 8) ws[lane] = s;
    }
    __syncthreads();
    int base = (w > 0) ? ws[w - 1] : 0;
    return base + x - v;   // exclusive
}

__global__ void k_scan1(const int* __restrict__ cnt, int* __restrict__ bsum, int n) {
    int tid = threadIdx.x;
    int i = blockIdx.x * 256 + tid;
    int v = (i < n) ? cnt[i] : 0;
    #pragma unroll
    for (int o = 16; o; o >>= 1) v += __shfl_down_sync(0xffffffffu, v, o);
    __shared__ int ws[8];
    if ((tid & 31) == 0) ws[tid >> 5] = v;
    __syncthreads();
    if (tid < 8) {
        int s = ws[tid];
        #pragma unroll
        for (int o = 4; o; o >>= 1) s += __shfl_down_sync(0xffu, s, o);
        if (tid == 0) bsum[blockIdx.x] = s;
    }
}

__global__ void k_scan3(int* __restrict__ cnt, const int* __restrict__ bsum,
                        int* __restrict__ rows, float* __restrict__ dis, int n) {
    int tid = threadIdx.x;
    int bid = blockIdx.x;
    __shared__ int wsb[8];
    __shared__ int sbase;

    int bv = (tid < bid) ? bsum[tid] : 0;       // bid < 256 always
    #pragma unroll
    for (int o = 16; o; o >>= 1) bv += __shfl_down_sync(0xffffffffu, bv, o);
    if ((tid & 31) == 0) wsb[tid >> 5] = bv;
    __syncthreads();
    if (tid == 0) {
        int s = 0;
        #pragma unroll
        for (int w = 0; w < 8; w++) s += wsb[w];
        sbase = s;
    }
    __syncthreads();

    int i = bid * 256 + tid;
    int v = (i < n) ? cnt[i] : 0;
    int e = block_excl_scan256(v, tid) + sbase;
    if (i <= n) rows[i] = e;
    if (i < n) {
        dis[i] = rsqrtf((float)(v + 1));
        cnt[i] = 0;                              // ready for next call
    }
}

__global__ void k_fill(const int* __restrict__ src, const int* __restrict__ dst,
                       const int* __restrict__ rows, const int* __restrict__ rank,
                       int* __restrict__ csr, int e) {
    int i = (blockIdx.x * blockDim.x + threadIdx.x) * 4;
    if (i + 3 < e) {
        int4 s = *(const int4*)(src + i);
        int4 d = *(const int4*)(dst + i);
        int4 r = *(const int4*)(rank + i);
        int p0 = __ldg(rows + d.x) + r.x;
        int p1 = __ldg(rows + d.y) + r.y;
        int p2 = __ldg(rows + d.z) + r.z;
        int p3 = __ldg(rows + d.w) + r.w;
        csr[p0] = s.x; csr[p1] = s.y; csr[p2] = s.z; csr[p3] = s.w;
    } else {
        for (; i < e; i++) csr[__ldg(rows + dst[i]) + rank[i]] = src[i];
    }
}

// ---- GEMM  h = fp16( [dis *] (X @ W) ) -------------------------------------
// 128 threads/block, tile 128 rows x 64 cols, 8x8 per thread, K chunks of 32.
template <int K, bool SCALE>
__global__ void __launch_bounds__(128, 4)
k_gemm(const float* __restrict__ Xin, const float* __restrict__ W,
       const float* __restrict__ dis, __half* __restrict__ h, int M) {
    constexpr int NCH = K / 32;
    __shared__ float  Xs [128 * 33];
    __shared__ float4 Ws4[32 * 16];

    int tid = threadIdx.x;
    int tx  = tid & 7;
    int ty  = tid >> 3;
    int m0  = blockIdx.x * 128;

    float acc[8][8];
    #pragma unroll
    for (int j = 0; j < 8; j++)
        #pragma unroll
        for (int i = 0; i < 8; i++) acc[j][i] = 0.f;

    const float4* W4 = (const float4*)W;

    #pragma unroll
    for (int ch = 0; ch < NCH; ch++) {
        #pragma unroll
        for (int it = 0; it < 8; it++) {
            int i = tid + it * 128;
            int r = i >> 3, c = i & 7;
            int gr = m0 + r;
            float4 v = make_float4(0.f, 0.f, 0.f, 0.f);
            if (gr < M) v = __ldg((const float4*)(Xin + (size_t)gr * K) + ch * 8 + c);
            float* p = Xs + r * 33 + c * 4;
            p[0] = v.x; p[1] = v.y; p[2] = v.z; p[3] = v.w;
        }
        #pragma unroll
        for (int it = 0; it < 4; it++) {
            int i = tid + it * 128;
            Ws4[i] = __ldg(W4 + ch * 512 + i);
        }
        __syncthreads();

        #pragma unroll 8
        for (int k = 0; k < 32; k++) {
            float a[8];
            #pragma unroll
            for (int j = 0; j < 8; j++) a[j] = Xs[(ty * 8 + j) * 33 + k];
            float4 w0 = Ws4[k * 16 + tx];
            float4 w1 = Ws4[k * 16 + 8 + tx];
            #pragma unroll
            for (int j = 0; j < 8; j++) {
                acc[j][0] += a[j] * w0.x;
                acc[j][1] += a[j] * w0.y;
                acc[j][2] += a[j] * w0.z;
                acc[j][3] += a[j] * w0.w;
                acc[j][4] += a[j] * w1.x;
                acc[j][5] += a[j] * w1.y;
                acc[j][6] += a[j] * w1.z;
                acc[j][7] += a[j] * w1.w;
            }
        }
        if (ch + 1 < NCH) __syncthreads();
    }

    #pragma unroll
    for (int j = 0; j < 8; j++) {
        int gr = m0 + ty * 8 + j;
        if (gr < M) {
            float dd = SCALE ? __ldg(dis + gr) : 1.0f;
            __half2 h0 = __floats2half2_rn(acc[j][0] * dd, acc[j][1] * dd);
            __half2 h1 = __floats2half2_rn(acc[j][2] * dd, acc[j][3] * dd);
            __half2 h2 = __floats2half2_rn(acc[j][4] * dd, acc[j][5] * dd);
            __half2 h3 = __floats2half2_rn(acc[j][6] * dd, acc[j][7] * dd);
            uint2 u0, u1;
            u0.x = *reinterpret_cast<unsigned*>(&h0);
            u0.y = *reinterpret_cast<unsigned*>(&h1);
            u1.x = *reinterpret_cast<unsigned*>(&h2);
            u1.y = *reinterpret_cast<unsigned*>(&h3);
            uint2* hp = (uint2*)(h + (size_t)gr * 64);
            hp[tx]     = u0;
            hp[8 + tx] = u1;
        }
    }
}

// ---- gather helpers (8 lanes per node, 16B per lane) -----------------------
__device__ __forceinline__ void acc_h8(float* acc, uint4 u, float s) {
    __half2* hp = (__half2*)&u;
    #pragma unroll
    for (int t = 0; t < 4; t++) {
        float2 f = __half22float2(hp[t]);
        acc[2 * t]     += s * f.x;
        acc[2 * t + 1] += s * f.y;
    }
}

// SRCS: h is unscaled; weight each row by dis[row]. Else h pre-scaled.
template <bool SRCS>
__device__ __forceinline__ void gather_row8(const int* __restrict__ rows,
                                            const int* __restrict__ csr,
                                            const __half* __restrict__ h,
                                            const float* __restrict__ dis,
                                            int g, int lane, float dd,
                                            float* acc) {
    int s0 = __ldg(rows + g);
    int s1 = __ldg(rows + g + 1);
    uint4 us = __ldg((const uint4*)(h + (size_t)g * 64) + lane);
    acc_h8(acc, us, SRCS ? dd : 1.0f);          // self-loop

    int j = s0;
    for (; j + 4 <= s1; j += 4) {
        int i0 = __ldg(csr + j);
        int i1 = __ldg(csr + j + 1);
        int i2 = __ldg(csr + j + 2);
        int i3 = __ldg(csr + j + 3);
        float d0 = SRCS ? __ldg(dis + i0) : 1.0f;
        float d1 = SRCS ? __ldg(dis + i1) : 1.0f;
        float d2 = SRCS ? __ldg(dis + i2) : 1.0f;
        float d3 = SRCS ? __ldg(dis + i3) : 1.0f;
        uint4 u0 = __ldg((const uint4*)(h + (size_t)i0 * 64) + lane);
        uint4 u1 = __ldg((const uint4*)(h + (size_t)i1 * 64) + lane);
        uint4 u2 = __ldg((const uint4*)(h + (size_t)i2 * 64) + lane);
        uint4 u3 = __ldg((const uint4*)(h + (size_t)i3 * 64) + lane);
        acc_h8(acc, u0, d0);
        acc_h8(acc, u1, d1);
        acc_h8(acc, u2, d2);
        acc_h8(acc, u3, d3);
    }
    for (; j < s1; j++) {
        int i0 = __ldg(csr + j);
        float d0 = SRCS ? __ldg(dis + i0) : 1.0f;
        uint4 u0 = __ldg((const uint4*)(h + (size_t)i0 * 64) + lane);
        acc_h8(acc, u0, d0);
    }
}

// ---- gather (layers 1,2): xout[g] = relu(dis[g]*sum + b) -------------------
template <bool SRCS>
__global__ void __launch_bounds__(256)
k_gather(const int* __restrict__ rows, const int* __restrict__ csr,
         const __half* __restrict__ h, const float* __restrict__ dis,
         const float* __restrict__ b, float* __restrict__ xout, int M) {
    int g = blockIdx.x * 32 + (threadIdx.x >> 3);
    if (g >= M) return;
    int lane = threadIdx.x & 7;

    float dd = __ldg(dis + g);
    float acc[8];
    #pragma unroll
    for (int t = 0; t < 8; t++) acc[t] = 0.f;
    gather_row8<SRCS>(rows, csr, h, dis, g, lane, dd, acc);

    float4 b0 = __ldg((const float4*)b + 2 * lane);
    float4 b1 = __ldg((const float4*)b + 2 * lane + 1);
    float4 o0, o1;
    o0.x = fmaxf(acc[0] * dd + b0.x, 0.f);
    o0.y = fmaxf(acc[1] * dd + b0.y, 0.f);
    o0.z = fmaxf(acc[2] * dd + b0.z, 0.f);
    o0.w = fmaxf(acc[3] * dd + b0.w, 0.f);
    o1.x = fmaxf(acc[4] * dd + b1.x, 0.f);
    o1.y = fmaxf(acc[5] * dd + b1.y, 0.f);
    o1.z = fmaxf(acc[6] * dd + b1.z, 0.f);
    o1.w = fmaxf(acc[7] * dd + b1.w, 0.f);
    float4* op = (float4*)(xout + (size_t)g * 64);
    op[2 * lane]     = o0;
    op[2 * lane + 1] = o1;
}

// ---- layer-3 gather fused with classifier ----------------------------------
__global__ void __launch_bounds__(256)
k_gather_classify(const int* __restrict__ rows, const int* __restrict__ csr,
                  const __half* __restrict__ h, const float* __restrict__ dis,
                  const float* __restrict__ b3,
                  const float* __restrict__ x1, const float* __restrict__ x2,
                  const float* __restrict__ Wl, const float* __restrict__ bl,
                  float* __restrict__ out, int M) {
    __shared__ float sW[8 * 192];   // sW[c*192 + f]
    __shared__ float sb[8];
    int tid = threadIdx.x;
    for (int i = tid; i < 192 * 8; i += 256) {
        int f = i >> 3, c = i & 7;
        sW[c * 192 + f] = Wl[i];
    }
    if (tid < 8) sb[tid] = bl[tid];
    __syncthreads();

    int g = blockIdx.x * 32 + (tid >> 3);
    if (g >= M) return;
    int lane = tid & 7;

    float dd = __ldg(dis + g);
    float acc[8];
    #pragma unroll
    for (int t = 0; t < 8; t++) acc[t] = 0.f;
    gather_row8<false>(rows, csr, h, dis, g, lane, dd, acc);

    float4 b0 = __ldg((const float4*)b3 + 2 * lane);
    float4 b1 = __ldg((const float4*)b3 + 2 * lane + 1);
    float x3v[8];
    x3v[0] = acc[0] * dd + b0.x;  x3v[1] = acc[1] * dd + b0.y;
    x3v[2] = acc[2] * dd + b0.z;  x3v[3] = acc[3] * dd + b0.w;
    x3v[4] = acc[4] * dd + b1.x;  x3v[5] = acc[5] * dd + b1.y;
    x3v[6] = acc[6] * dd + b1.z;  x3v[7] = acc[7] * dd + b1.w;

    float4 v10 = __ldg((const float4*)(x1 + (size_t)g * 64) + 2 * lane);
    float4 v11 = __ldg((const float4*)(x1 + (size_t)g * 64) + 2 * lane + 1);
    float4 v20 = __ldg((const float4*)(x2 + (size_t)g * 64) + 2 * lane);
    float4 v21 = __ldg((const float4*)(x2 + (size_t)g * 64) + 2 * lane + 1);
    float x1v[8] = {v10.x, v10.y, v10.z, v10.w, v11.x, v11.y, v11.z, v11.w};
    float x2v[8] = {v20.x, v20.y, v20.z, v20.w, v21.x, v21.y, v21.z, v21.w};

    unsigned mask = 0xFFu << (tid & 0x18);   // this thread's 8-lane group

    float lg[8];
    #pragma unroll
    for (int c = 0; c < 8; c++) {
        const float* w = sW + c * 192 + 8 * lane;
        float s = 0.f;
        #pragma unroll
        for (int j = 0; j < 8; j++) {
            s += x1v[j] * w[j];
            s += x2v[j] * w[64 + j];
            s += x3v[j] * w[128 + j];
        }
        #pragma unroll
        for (int o = 4; o; o >>= 1)
            s += __shfl_xor_sync(mask, s, o, 8);
        lg[c] = s;
    }

    if (lane == 0) {
        float m = -INFINITY;
        #pragma unroll
        for (int c = 0; c < 8; c++) { lg[c] += sb[c]; m = fmaxf(m, lg[c]); }
        float s = 0.f;
        #pragma unroll
        for (int c = 0; c < 8; c++) s += expf(lg[c] - m);
        float lse = logf(s) + m;
        #pragma unroll
        for (int c = 0; c < 8; c++) out[(size_t)g * 8 + c] = lg[c] - lse;
    }
}

// ---------------------------------------------------------------------------
extern "C" void kernel_launch(void* const* d_in, const int* in_sizes, int n_in,
                              void* d_out, int out_size) {
    const float* x  = (const float*)d_in[0];
    const int*   ei = (const int*)  d_in[1];
    const float* W1 = (const float*)d_in[2];
    const float* b1 = (const float*)d_in[3];
    const float* W2 = (const float*)d_in[4];
    const float* b2 = (const float*)d_in[5];
    const float* W3 = (const float*)d_in[6];
    const float* b3 = (const float*)d_in[7];
    const float* Wl = (const float*)d_in[8];
    const float* bl = (const float*)d_in[9];
    float* out = (float*)d_out;

    int N = in_sizes[0] / 128;
    int E = in_sizes[1] / 2;
    const int* src = ei;
    const int* dst = ei + E;

    float *dis, *x1, *x2;
    __half* h;
    int *cnt, *rows, *rank, *bsum, *csr;
    cudaGetSymbolAddress((void**)&dis,  g_dis);
    cudaGetSymbolAddress((void**)&h,    g_h);
    cudaGetSymbolAddress((void**)&x1,   g_x1);
    cudaGetSymbolAddress((void**)&x2,   g_x2);
    cudaGetSymbolAddress((void**)&cnt,  g_cnt);
    cudaGetSymbolAddress((void**)&rows, g_rows);
    cudaGetSymbolAddress((void**)&rank, g_rank);
    cudaGetSymbolAddress((void**)&bsum, g_bsum);
    cudaGetSymbolAddress((void**)&csr,  g_csr);

    // one-time side-stream + events (work per call is identical; these are
    // host-side resources created once, before any capture uses them)
    static cudaStream_t s2 = nullptr;
    static cudaEvent_t evF = nullptr, evJ = nullptr;
    if (s2 == nullptr) {
        cudaStreamCreateWithFlags(&s2, cudaStreamNonBlocking);
        cudaEventCreateWithFlags(&evF, cudaEventDisableTiming);
        cudaEventCreateWithFlags(&evJ, cudaEventDisableTiming);
    }

    int nb1  = (N + 1 + 255) / 256;      // covers row_start[N]
    int e4b  = ((E + 3) / 4 + 255) / 256;
    int gb   = (N + 127) / 128;
    int gthb = (N + 31) / 32;

    // ---- fork: CSR build on s2, concurrent with layer-1 GEMM on stream 0 ---
    cudaEventRecord(evF, 0);
    cudaStreamWaitEvent(s2, evF, 0);

    k_hist <<<e4b, 256, 0, s2>>>(dst, cnt, rank, E);
    k_scan1<<<nb1, 256, 0, s2>>>(cnt, bsum, N);
    k_scan3<<<nb1, 256, 0, s2>>>(cnt, bsum, rows, dis, N);
    k_fill <<<e4b, 256, 0, s2>>>(src, dst, rows, rank, csr, E);
    cudaEventRecord(evJ, s2);

    // layer-1 GEMM (unscaled h; independent of CSR/dis)
    k_gemm<128, false><<<gb, 128>>>(x, W1, nullptr, h, N);

    cudaStreamWaitEvent(0, evJ, 0);      // join

    // layer 1 aggregate: dis applied per-source inside gather
    k_gather<true><<<gthb, 256>>>(rows, csr, h, dis, b1, x1, N);

    // layer 2: 64 -> 64, relu (h pre-scaled)
    k_gemm<64, true><<<gb, 128>>>(x1, W2, dis, h, N);
    k_gather<false><<<gthb, 256>>>(rows, csr, h, dis, b2, x2, N);

    // layer 3: 64 -> 64 + classifier (fused)
    k_gemm<64, true><<<gb, 128>>>(x2, W3, dis, h, N);
    k_gather_classify<<<gthb, 256>>>(rows, csr, h, dis, b3, x1, x2,
                                     Wl, bl, out, N);
}

// round 7
// speedup vs baseline: 3.1055x; 1.1726x over previous
#include <cuda_runtime.h>
#include <cuda_fp16.h>
#include <math.h>

// ---------------------------------------------------------------------------
// GCN: 3x GCNConv (128->64->64->64) + concat(192) @ Wl(192x8) + log_softmax
// Destination-CSR gather (atomic-free fill), fp16 messages, fp32 accumulate.
// CSR build + W34 precompute overlapped with layer-1 GEMM (forked stream).
// Layer 3 (no relu) folded through the classifier:
//   p = dis*(x2 @ (W3@Wl3)) [N,8];  logits3 = dis_d*(p_d + sum p_s) + b3@Wl3
// ---------------------------------------------------------------------------

#define N_NODES_MAX 50000
#define E_MAX       800000

__device__ float  g_dis [N_NODES_MAX];
__device__ __half g_h   [N_NODES_MAX * 64];
__device__ float  g_x1  [N_NODES_MAX * 64];
__device__ float  g_x2  [N_NODES_MAX * 64];
__device__ float  g_p   [N_NODES_MAX * 8];
__device__ int    g_cnt [N_NODES_MAX];         // zeroed at end of each call
__device__ int    g_rows[N_NODES_MAX + 1];
__device__ int    g_rank[E_MAX];
__device__ int    g_bsum[256];
__device__ int    g_csr [E_MAX];
__device__ float  g_W34 [64 * 8];
__device__ float  g_c3  [8];

// ---- tiny precompute: W34 = W3 @ Wl[128:192], c3 = bl + b3 @ Wl[128:192] ---
__global__ void k_w3wl(const float* __restrict__ W3, const float* __restrict__ Wl,
                       const float* __restrict__ b3, const float* __restrict__ bl,
                       float* __restrict__ W34, float* __restrict__ c3) {
    int t = threadIdx.x;            // 512 threads: t = k*8 + c
    int k = t >> 3, c = t & 7;
    const float* wl3 = Wl + 128 * 8;
    float s = 0.f;
    #pragma unroll 8
    for (int j = 0; j < 64; j++) s += W3[k * 64 + j] * wl3[j * 8 + c];
    W34[t] = s;
    if (t < 8) {
        float cc = bl[t];
        for (int j = 0; j < 64; j++) cc += b3[j] * wl3[j * 8 + t];
        c3[t] = cc;
    }
}

// ---- CSR build (1 edge/thread: occupancy beats per-thread MLP here) --------
__global__ void k_hist(const int* __restrict__ dst, int* __restrict__ cnt,
                       int* __restrict__ rank, int e) {
    int i = blockIdx.x * blockDim.x + threadIdx.x;
    if (i < e) rank[i] = atomicAdd(&cnt[dst[i]], 1);
}

__device__ __forceinline__ int block_excl_scan256(int v, int tid) {
    __shared__ int ws[8];
    int lane = tid & 31, w = tid >> 5;
    int x = v;
    #pragma unroll
    for (int o = 1; o < 32; o <<= 1) {
        int y = __shfl_up_sync(0xffffffffu, x, o);
        if (lane >= o) x += y;
    }
    if (lane == 31) ws[w] = x;
    __syncthreads();
    if (w == 0) {
        int s = (lane < 8) ? ws[lane] : 0;
        #pragma unroll
        for (int o = 1; o < 8; o <<= 1) {
            int y = __shfl_up_sync(0xffffffffu, s, o);
            if (lane >= o) s += y;
        }
        if (lane < 8) ws[lane] = s;
    }
    __syncthreads();
    int base = (w > 0) ? ws[w - 1] : 0;
    return base + x - v;   // exclusive
}

__global__ void k_scan1(const int* __restrict__ cnt, int* __restrict__ bsum, int n) {
    int tid = threadIdx.x;
    int i = blockIdx.x * 256 + tid;
    int v = (i < n) ? cnt[i] : 0;
    #pragma unroll
    for (int o = 16; o; o >>= 1) v += __shfl_down_sync(0xffffffffu, v, o);
    __shared__ int ws[8];
    if ((tid & 31) == 0) ws[tid >> 5] = v;
    __syncthreads();
    if (tid < 8) {
        int s = ws[tid];
        #pragma unroll
        for (int o = 4; o; o >>= 1) s += __shfl_down_sync(0xffu, s, o);
        if (tid == 0) bsum[blockIdx.x] = s;
    }
}

__global__ void k_scan3(int* __restrict__ cnt, const int* __restrict__ bsum,
                        int* __restrict__ rows, float* __restrict__ dis, int n) {
    int tid = threadIdx.x;
    int bid = blockIdx.x;
    __shared__ int wsb[8];
    __shared__ int sbase;

    int bv = (tid < bid) ? bsum[tid] : 0;       // bid < 256 always
    #pragma unroll
    for (int o = 16; o; o >>= 1) bv += __shfl_down_sync(0xffffffffu, bv, o);
    if ((tid & 31) == 0) wsb[tid >> 5] = bv;
    __syncthreads();
    if (tid == 0) {
        int s = 0;
        #pragma unroll
        for (int w = 0; w < 8; w++) s += wsb[w];
        sbase = s;
    }
    __syncthreads();

    int i = bid * 256 + tid;
    int v = (i < n) ? cnt[i] : 0;
    int e = block_excl_scan256(v, tid) + sbase;
    if (i <= n) rows[i] = e;
    if (i < n) {
        dis[i] = rsqrtf((float)(v + 1));
        cnt[i] = 0;                              // ready for next call
    }
}

__global__ void k_fill(const int* __restrict__ src, const int* __restrict__ dst,
                       const int* __restrict__ rows, const int* __restrict__ rank,
                       int* __restrict__ csr, int e) {
    int i = blockIdx.x * blockDim.x + threadIdx.x;
    if (i < e) csr[__ldg(rows + dst[i]) + rank[i]] = src[i];
}

// ---- GEMM  h = fp16( [dis *] (X @ W) ) -------------------------------------
template <int K, bool SCALE>
__global__ void __launch_bounds__(128, 4)
k_gemm(const float* __restrict__ Xin, const float* __restrict__ W,
       const float* __restrict__ dis, __half* __restrict__ h, int M) {
    constexpr int NCH = K / 32;
    __shared__ float  Xs [128 * 33];
    __shared__ float4 Ws4[32 * 16];

    int tid = threadIdx.x;
    int tx  = tid & 7;
    int ty  = tid >> 3;
    int m0  = blockIdx.x * 128;

    float acc[8][8];
    #pragma unroll
    for (int j = 0; j < 8; j++)
        #pragma unroll
        for (int i = 0; i < 8; i++) acc[j][i] = 0.f;

    const float4* W4 = (const float4*)W;

    #pragma unroll
    for (int ch = 0; ch < NCH; ch++) {
        #pragma unroll
        for (int it = 0; it < 8; it++) {
            int i = tid + it * 128;
            int r = i >> 3, c = i & 7;
            int gr = m0 + r;
            float4 v = make_float4(0.f, 0.f, 0.f, 0.f);
            if (gr < M) v = __ldg((const float4*)(Xin + (size_t)gr * K) + ch * 8 + c);
            float* p = Xs + r * 33 + c * 4;
            p[0] = v.x; p[1] = v.y; p[2] = v.z; p[3] = v.w;
        }
        #pragma unroll
        for (int it = 0; it < 4; it++) {
            int i = tid + it * 128;
            Ws4[i] = __ldg(W4 + ch * 512 + i);
        }
        __syncthreads();

        #pragma unroll 8
        for (int k = 0; k < 32; k++) {
            float a[8];
            #pragma unroll
            for (int j = 0; j < 8; j++) a[j] = Xs[(ty * 8 + j) * 33 + k];
            float4 w0 = Ws4[k * 16 + tx];
            float4 w1 = Ws4[k * 16 + 8 + tx];
            #pragma unroll
            for (int j = 0; j < 8; j++) {
                acc[j][0] += a[j] * w0.x;
                acc[j][1] += a[j] * w0.y;
                acc[j][2] += a[j] * w0.z;
                acc[j][3] += a[j] * w0.w;
                acc[j][4] += a[j] * w1.x;
                acc[j][5] += a[j] * w1.y;
                acc[j][6] += a[j] * w1.z;
                acc[j][7] += a[j] * w1.w;
            }
        }
        if (ch + 1 < NCH) __syncthreads();
    }

    #pragma unroll
    for (int j = 0; j < 8; j++) {
        int gr = m0 + ty * 8 + j;
        if (gr < M) {
            float dd = SCALE ? __ldg(dis + gr) : 1.0f;
            __half2 h0 = __floats2half2_rn(acc[j][0] * dd, acc[j][1] * dd);
            __half2 h1 = __floats2half2_rn(acc[j][2] * dd, acc[j][3] * dd);
            __half2 h2 = __floats2half2_rn(acc[j][4] * dd, acc[j][5] * dd);
            __half2 h3 = __floats2half2_rn(acc[j][6] * dd, acc[j][7] * dd);
            uint2 u0, u1;
            u0.x = *reinterpret_cast<unsigned*>(&h0);
            u0.y = *reinterpret_cast<unsigned*>(&h1);
            u1.x = *reinterpret_cast<unsigned*>(&h2);
            u1.y = *reinterpret_cast<unsigned*>(&h3);
            uint2* hp = (uint2*)(h + (size_t)gr * 64);
            hp[tx]     = u0;
            hp[8 + tx] = u1;
        }
    }
}

// ---- gather helpers (8 lanes per node, 16B per lane) -----------------------
__device__ __forceinline__ void acc_h8(float* acc, uint4 u, float s) {
    __half2* hp = (__half2*)&u;
    #pragma unroll
    for (int t = 0; t < 4; t++) {
        float2 f = __half22float2(hp[t]);
        acc[2 * t]     += s * f.x;
        acc[2 * t + 1] += s * f.y;
    }
}

template <bool SRCS>
__device__ __forceinline__ void gather_row8(const int* __restrict__ rows,
                                            const int* __restrict__ csr,
                                            const __half* __restrict__ h,
                                            const float* __restrict__ dis,
                                            int g, int lane, float dd,
                                            float* acc) {
    int s0 = __ldg(rows + g);
    int s1 = __ldg(rows + g + 1);
    uint4 us = __ldg((const uint4*)(h + (size_t)g * 64) + lane);
    acc_h8(acc, us, SRCS ? dd : 1.0f);          // self-loop

    int j = s0;
    for (; j + 4 <= s1; j += 4) {
        int i0 = __ldg(csr + j);
        int i1 = __ldg(csr + j + 1);
        int i2 = __ldg(csr + j + 2);
        int i3 = __ldg(csr + j + 3);
        float d0 = SRCS ? __ldg(dis + i0) : 1.0f;
        float d1 = SRCS ? __ldg(dis + i1) : 1.0f;
        float d2 = SRCS ? __ldg(dis + i2) : 1.0f;
        float d3 = SRCS ? __ldg(dis + i3) : 1.0f;
        uint4 u0 = __ldg((const uint4*)(h + (size_t)i0 * 64) + lane);
        uint4 u1 = __ldg((const uint4*)(h + (size_t)i1 * 64) + lane);
        uint4 u2 = __ldg((const uint4*)(h + (size_t)i2 * 64) + lane);
        uint4 u3 = __ldg((const uint4*)(h + (size_t)i3 * 64) + lane);
        acc_h8(acc, u0, d0);
        acc_h8(acc, u1, d1);
        acc_h8(acc, u2, d2);
        acc_h8(acc, u3, d3);
    }
    for (; j < s1; j++) {
        int i0 = __ldg(csr + j);
        float d0 = SRCS ? __ldg(dis + i0) : 1.0f;
        uint4 u0 = __ldg((const uint4*)(h + (size_t)i0 * 64) + lane);
        acc_h8(acc, u0, d0);
    }
}

// ---- gather layer 1: x1[g] = relu(dis[g]*sum(dis[s]*h[s]) + b) -------------
__global__ void __launch_bounds__(256)
k_gather(const int* __restrict__ rows, const int* __restrict__ csr,
         const __half* __restrict__ h, const float* __restrict__ dis,
         const float* __restrict__ b, float* __restrict__ xout, int M) {
    int g = blockIdx.x * 32 + (threadIdx.x >> 3);
    if (g >= M) return;
    int lane = threadIdx.x & 7;

    float dd = __ldg(dis + g);
    float acc[8];
    #pragma unroll
    for (int t = 0; t < 8; t++) acc[t] = 0.f;
    gather_row8<true>(rows, csr, h, dis, g, lane, dd, acc);

    float4 b0 = __ldg((const float4*)b + 2 * lane);
    float4 b1 = __ldg((const float4*)b + 2 * lane + 1);
    float4 o0, o1;
    o0.x = fmaxf(acc[0] * dd + b0.x, 0.f);
    o0.y = fmaxf(acc[1] * dd + b0.y, 0.f);
    o0.z = fmaxf(acc[2] * dd + b0.z, 0.f);
    o0.w = fmaxf(acc[3] * dd + b0.w, 0.f);
    o1.x = fmaxf(acc[4] * dd + b1.x, 0.f);
    o1.y = fmaxf(acc[5] * dd + b1.y, 0.f);
    o1.z = fmaxf(acc[6] * dd + b1.z, 0.f);
    o1.w = fmaxf(acc[7] * dd + b1.w, 0.f);
    float4* op = (float4*)(xout + (size_t)g * 64);
    op[2 * lane]     = o0;
    op[2 * lane + 1] = o1;
}

// ---- gather layer 2 + p: x2 = relu(dis*sum + b2);  p = dis*(x2 @ W34) ------
__global__ void __launch_bounds__(256)
k_gather2p(const int* __restrict__ rows, const int* __restrict__ csr,
           const __half* __restrict__ h, const float* __restrict__ dis,
           const float* __restrict__ b, const float* __restrict__ W34,
           float* __restrict__ xout, float* __restrict__ p, int M) {
    __shared__ float swt[8 * 64];   // swt[c*64 + f] = W34[f*8+c]
    int tid = threadIdx.x;
    {
        int i = tid;          swt[(i & 7) * 64 + (i >> 3)] = __ldg(W34 + i);
        i = tid + 256;        swt[(i & 7) * 64 + (i >> 3)] = __ldg(W34 + i);
    }
    __syncthreads();

    int g = blockIdx.x * 32 + (tid >> 3);
    if (g >= M) return;
    int lane = tid & 7;
    unsigned mask = 0xFFu << (tid & 0x18);

    float dd = __ldg(dis + g);
    float acc[8];
    #pragma unroll
    for (int t = 0; t < 8; t++) acc[t] = 0.f;
    gather_row8<false>(rows, csr, h, dis, g, lane, dd, acc);

    float4 b0 = __ldg((const float4*)b + 2 * lane);
    float4 b1 = __ldg((const float4*)b + 2 * lane + 1);
    float4 o0, o1;
    o0.x = fmaxf(acc[0] * dd + b0.x, 0.f);
    o0.y = fmaxf(acc[1] * dd + b0.y, 0.f);
    o0.z = fmaxf(acc[2] * dd + b0.z, 0.f);
    o0.w = fmaxf(acc[3] * dd + b0.w, 0.f);
    o1.x = fmaxf(acc[4] * dd + b1.x, 0.f);
    o1.y = fmaxf(acc[5] * dd + b1.y, 0.f);
    o1.z = fmaxf(acc[6] * dd + b1.z, 0.f);
    o1.w = fmaxf(acc[7] * dd + b1.w, 0.f);
    float4* op = (float4*)(xout + (size_t)g * 64);
    op[2 * lane]     = o0;
    op[2 * lane + 1] = o1;

    // p[c] = dd * sum_f x2[f]*W34[f][c]; this lane holds features lane*8..+7
    float part[8];
    #pragma unroll
    for (int cc = 0; cc < 8; cc++) {
        const float4* w = (const float4*)(swt + cc * 64 + lane * 8);
        float4 wa = w[0], wb = w[1];
        part[cc] = o0.x * wa.x + o0.y * wa.y + o0.z * wa.z + o0.w * wa.w
                 + o1.x * wb.x + o1.y * wb.y + o1.z * wb.z + o1.w * wb.w;
    }
    #pragma unroll
    for (int o = 4; o; o >>= 1)
        #pragma unroll
        for (int cc = 0; cc < 8; cc++)
            part[cc] += __shfl_xor_sync(mask, part[cc], o, 8);
    p[(size_t)g * 8 + lane] = dd * part[lane];
}

// ---- classifier with folded layer 3 ----------------------------------------
// logit_c = x1.Wl1[c] + x2.Wl2[c] + dis_g*(p[g][c] + sum_s p[s][c]) + c3[c]
__global__ void __launch_bounds__(256)
k_classify_p(const int* __restrict__ rows, const int* __restrict__ csr,
             const float* __restrict__ p, const float* __restrict__ dis,
             const float* __restrict__ x1, const float* __restrict__ x2,
             const float* __restrict__ Wl, const float* __restrict__ c3,
             float* __restrict__ out, int M) {
    __shared__ float sW1[8 * 64];   // sW1[c*64+f] = Wl[f*8+c]
    __shared__ float sW2[8 * 64];   // sW2[c*64+f] = Wl[(64+f)*8+c]
    __shared__ float sc3[8];
    int tid = threadIdx.x;
    {
        int i = tid;   sW1[(i & 7) * 64 + (i >> 3)] = __ldg(Wl + i);
        i = tid + 256; sW1[(i & 7) * 64 + (i >> 3)] = __ldg(Wl + i);
        i = tid;       sW2[(i & 7) * 64 + (i >> 3)] = __ldg(Wl + 512 + i);
        i = tid + 256; sW2[(i & 7) * 64 + (i >> 3)] = __ldg(Wl + 512 + i);
    }
    if (tid < 8) sc3[tid] = __ldg(c3 + tid);
    __syncthreads();

    int g = blockIdx.x * 32 + (tid >> 3);
    if (g >= M) return;
    int c = tid & 7;
    unsigned mask = 0xFFu << (tid & 0x18);

    // folded layer-3 gather: lane c accumulates class c
    int s0 = __ldg(rows + g);
    int s1 = __ldg(rows + g + 1);
    float pc  = __ldg(p + (size_t)g * 8 + c);
    float pc2 = 0.f;
    int j = s0;
    for (; j + 2 <= s1; j += 2) {
        int i0 = __ldg(csr + j);
        int i1 = __ldg(csr + j + 1);
        pc  += __ldg(p + (size_t)i0 * 8 + c);
        pc2 += __ldg(p + (size_t)i1 * 8 + c);
    }
    if (j < s1) pc += __ldg(p + (size_t)__ldg(csr + j) * 8 + c);
    pc += pc2;

    // dense part: this lane covers features c*8..c*8+7
    float4 a0 = __ldg((const float4*)(x1 + (size_t)g * 64) + 2 * c);
    float4 a1 = __ldg((const float4*)(x1 + (size_t)g * 64) + 2 * c + 1);
    float4 e0 = __ldg((const float4*)(x2 + (size_t)g * 64) + 2 * c);
    float4 e1 = __ldg((const float4*)(x2 + (size_t)g * 64) + 2 * c + 1);

    float part[8];
    #pragma unroll
    for (int cc = 0; cc < 8; cc++) {
        const float4* w1 = (const float4*)(sW1 + cc * 64 + c * 8);
        const float4* w2 = (const float4*)(sW2 + cc * 64 + c * 8);
        float4 wa = w1[0], wb = w1[1], wc = w2[0], wd = w2[1];
        part[cc] = a0.x * wa.x + a0.y * wa.y + a0.z * wa.z + a0.w * wa.w
                 + a1.x * wb.x + a1.y * wb.y + a1.z * wb.z + a1.w * wb.w
                 + e0.x * wc.x + e0.y * wc.y + e0.z * wc.z + e0.w * wc.w
                 + e1.x * wd.x + e1.y * wd.y + e1.z * wd.z + e1.w * wd.w;
    }
    #pragma unroll
    for (int o = 4; o; o >>= 1)
        #pragma unroll
        for (int cc = 0; cc < 8; cc++)
            part[cc] += __shfl_xor_sync(mask, part[cc], o, 8);

    float logit = part[c] + __ldg(dis + g) * pc + sc3[c];

    // softmax across the 8 lanes (lane = class)
    float m = logit;
    #pragma unroll
    for (int o = 4; o; o >>= 1) m = fmaxf(m, __shfl_xor_sync(mask, m, o, 8));
    float ex = expf(logit - m);
    float s = ex;
    #pragma unroll
    for (int o = 4; o; o >>= 1) s += __shfl_xor_sync(mask, s, o, 8);
    out[(size_t)g * 8 + c] = logit - (logf(s) + m);
}

// ---------------------------------------------------------------------------
extern "C" void kernel_launch(void* const* d_in, const int* in_sizes, int n_in,
                              void* d_out, int out_size) {
    const float* x  = (const float*)d_in[0];
    const int*   ei = (const int*)  d_in[1];
    const float* W1 = (const float*)d_in[2];
    const float* b1 = (const float*)d_in[3];
    const float* W2 = (const float*)d_in[4];
    const float* b2 = (const float*)d_in[5];
    const float* W3 = (const float*)d_in[6];
    const float* b3 = (const float*)d_in[7];
    const float* Wl = (const float*)d_in[8];
    const float* bl = (const float*)d_in[9];
    float* out = (float*)d_out;

    int N = in_sizes[0] / 128;
    int E = in_sizes[1] / 2;
    const int* src = ei;
    const int* dst = ei + E;

    float *dis, *x1, *x2, *p, *W34, *c3;
    __half* h;
    int *cnt, *rows, *rank, *bsum, *csr;
    cudaGetSymbolAddress((void**)&dis,  g_dis);
    cudaGetSymbolAddress((void**)&h,    g_h);
    cudaGetSymbolAddress((void**)&x1,   g_x1);
    cudaGetSymbolAddress((void**)&x2,   g_x2);
    cudaGetSymbolAddress((void**)&p,    g_p);
    cudaGetSymbolAddress((void**)&W34,  g_W34);
    cudaGetSymbolAddress((void**)&c3,   g_c3);
    cudaGetSymbolAddress((void**)&cnt,  g_cnt);
    cudaGetSymbolAddress((void**)&rows, g_rows);
    cudaGetSymbolAddress((void**)&rank, g_rank);
    cudaGetSymbolAddress((void**)&bsum, g_bsum);
    cudaGetSymbolAddress((void**)&csr,  g_csr);

    static cudaStream_t s2 = nullptr;
    static cudaEvent_t evF = nullptr, evJ = nullptr;
    if (s2 == nullptr) {
        cudaStreamCreateWithFlags(&s2, cudaStreamNonBlocking);
        cudaEventCreateWithFlags(&evF, cudaEventDisableTiming);
        cudaEventCreateWithFlags(&evJ, cudaEventDisableTiming);
    }

    int nb1  = (N + 1 + 255) / 256;
    int eb   = (E + 255) / 256;
    int gb   = (N + 127) / 128;
    int gthb = (N + 31) / 32;

    // ---- fork: CSR build + W34 precompute on s2, concurrent with GEMM1 -----
    cudaEventRecord(evF, 0);
    cudaStreamWaitEvent(s2, evF, 0);

    k_w3wl <<<1, 512, 0, s2>>>(W3, Wl, b3, bl, W34, c3);
    k_hist <<<eb, 256, 0, s2>>>(dst, cnt, rank, E);
    k_scan1<<<nb1, 256, 0, s2>>>(cnt, bsum, N);
    k_scan3<<<nb1, 256, 0, s2>>>(cnt, bsum, rows, dis, N);
    k_fill <<<eb, 256, 0, s2>>>(src, dst, rows, rank, csr, E);
    cudaEventRecord(evJ, s2);

    // layer-1 GEMM (unscaled h; independent of CSR/dis)
    k_gemm<128, false><<<gb, 128>>>(x, W1, nullptr, h, N);

    cudaStreamWaitEvent(0, evJ, 0);      // join

    // layer 1 aggregate (dis applied per-source)
    k_gather<<<gthb, 256>>>(rows, csr, h, dis, b1, x1, N);

    // layer 2 GEMM + aggregate (also emits p = dis*(x2@W34))
    k_gemm<64, true><<<gb, 128>>>(x1, W2, dis, h, N);
    k_gather2p<<<gthb, 256>>>(rows, csr, h, dis, b2, W34, x2, p, N);

    // classifier with folded layer 3
    k_classify_p<<<gthb, 256>>>(rows, csr, p, dis, x1, x2, Wl, c3, out, N);
}